// round 2
// baseline (speedup 1.0000x reference)
#include <cuda_runtime.h>
#include <math_constants.h>

#define Bn 16
#define Sn 2048
#define Dn 1024
#define Hn 64

#define APAD 132   // padded tile row stride (16B-aligned, kills store bank conflicts)

// ---------------- scratch (device globals; no allocations allowed) ----------
__device__ float g_h[(size_t)Bn * Sn * Hn];        //   8 MB  relu(query@w1+b1)
__device__ float g_q[(size_t)Bn * Sn * Dn];        // 134 MB  query proj
__device__ float g_k[(size_t)Bn * Sn * Dn];        // 134 MB  key proj
__device__ float g_logits[(size_t)Bn * Sn * Sn];   // 256 MB  logits
__device__ float g_w2t[Sn * Hn];                   // 512 KB  w2 transposed [S,H]

// ---------------- 16-deep fragment compute over one k-chunk ------------------
#define COMPUTE_CHUNK(AS, BS)                                                  \
    _Pragma("unroll")                                                          \
    for (int kk = 0; kk < 16; ++kk) {                                          \
        float a[8], bb[8];                                                     \
        *(float4*)&a[0]  = *(const float4*)&AS[kk][ty * 8];                    \
        *(float4*)&a[4]  = *(const float4*)&AS[kk][ty * 8 + 4];                \
        *(float4*)&bb[0] = *(const float4*)&BS[kk][tx * 8];                    \
        *(float4*)&bb[4] = *(const float4*)&BS[kk][tx * 8 + 4];                \
        _Pragma("unroll") for (int i = 0; i < 8; ++i)                          \
            _Pragma("unroll") for (int j = 0; j < 8; ++j)                      \
                acc[i][j] += a[i] * bb[j];                                     \
    }

#define STORE_A_TRANS(DST, V, ROW, KQ)                                         \
    DST[(KQ) + 0][ROW] = (V).x;  DST[(KQ) + 1][ROW] = (V).y;                   \
    DST[(KQ) + 2][ROW] = (V).z;  DST[(KQ) + 3][ROW] = (V).w;

// ---------------- double-buffered 128x128x16 SGEMM (NN), bias/relu ----------
template <bool RELU, bool BIAS>
__global__ void __launch_bounds__(256, 2)
sgemm_nn(const float* __restrict__ A, const float* __restrict__ B,
         const float* __restrict__ bias, float* __restrict__ C,
         int M, int N, int K,
         long long strideA, long long strideB, long long strideC)
{
    A += (size_t)blockIdx.z * strideA;
    B += (size_t)blockIdx.z * strideB;
    C += (size_t)blockIdx.z * strideC;

    __shared__ float As[2][16][APAD];
    __shared__ float Bs[2][16][128];

    const int tid = threadIdx.x;
    const int bm = blockIdx.y * 128;
    const int bn = blockIdx.x * 128;
    const int tx = tid & 15;
    const int ty = tid >> 4;

    // A loader: 512 float4 (128 rows x 4 vec); thread covers vec tid and tid+256
    const int arow0 = tid >> 2;
    const int arow1 = arow0 + 64;
    const int akq   = (tid & 3) * 4;
    // B loader: 512 float4 (16 rows x 32 vec)
    const int brow0 = tid >> 5;
    const int brow1 = brow0 + 8;
    const int bcol  = (tid & 31) * 4;
    const bool bok  = (bn + bcol) < N;

    float acc[8][8];
#pragma unroll
    for (int i = 0; i < 8; ++i)
#pragma unroll
        for (int j = 0; j < 8; ++j) acc[i][j] = 0.f;

    const int nchunk = K >> 4;
    const float4 z4 = make_float4(0.f, 0.f, 0.f, 0.f);

    {   // preload chunk 0 into buffer 0
        float4 a0 = *(const float4*)(A + (size_t)(bm + arow0) * K + akq);
        float4 a1 = *(const float4*)(A + (size_t)(bm + arow1) * K + akq);
        float4 b0 = bok ? *(const float4*)(B + (size_t)brow0 * N + bn + bcol) : z4;
        float4 b1 = bok ? *(const float4*)(B + (size_t)brow1 * N + bn + bcol) : z4;
        STORE_A_TRANS(As[0], a0, arow0, akq);
        STORE_A_TRANS(As[0], a1, arow1, akq);
        *(float4*)&Bs[0][brow0][bcol] = b0;
        *(float4*)&Bs[0][brow1][bcol] = b1;
    }
    __syncthreads();

    for (int t = 0; t < nchunk; ++t) {
        const int buf = t & 1;
        float4 a0, a1, b0, b1;
        const bool more = (t + 1 < nchunk);
        if (more) {   // prefetch next chunk while this one computes
            const int k0 = (t + 1) << 4;
            a0 = *(const float4*)(A + (size_t)(bm + arow0) * K + k0 + akq);
            a1 = *(const float4*)(A + (size_t)(bm + arow1) * K + k0 + akq);
            b0 = bok ? *(const float4*)(B + (size_t)(k0 + brow0) * N + bn + bcol) : z4;
            b1 = bok ? *(const float4*)(B + (size_t)(k0 + brow1) * N + bn + bcol) : z4;
        }
        COMPUTE_CHUNK(As[buf], Bs[buf]);
        if (more) {
            const int nb = buf ^ 1;
            STORE_A_TRANS(As[nb], a0, arow0, akq);
            STORE_A_TRANS(As[nb], a1, arow1, akq);
            *(float4*)&Bs[nb][brow0][bcol] = b0;
            *(float4*)&Bs[nb][brow1][bcol] = b1;
            __syncthreads();
        }
    }

#pragma unroll
    for (int i = 0; i < 8; ++i) {
        const int row = bm + ty * 8 + i;
        const int col = bn + tx * 8;
#pragma unroll
        for (int h = 0; h < 2; ++h) {
            if (col + h * 4 < N) {
                float4 v = *(float4*)&acc[i][h * 4];
                if (BIAS) {
                    const float4 bi = *(const float4*)(bias + col + h * 4);
                    v.x += bi.x; v.y += bi.y; v.z += bi.z; v.w += bi.w;
                }
                if (RELU) {
                    v.x = fmaxf(v.x, 0.f); v.y = fmaxf(v.y, 0.f);
                    v.z = fmaxf(v.z, 0.f); v.w = fmaxf(v.w, 0.f);
                }
                *(float4*)(C + (size_t)row * N + col + h * 4) = v;
            }
        }
    }
}

// ---------------- energy: logits = q@k^T + h@w2t^T + b2 (NT, fused) ---------
__global__ void __launch_bounds__(256, 2)
energy_kernel(const float* __restrict__ q, const float* __restrict__ k,
              const float* __restrict__ h, const float* __restrict__ w2t,
              const float* __restrict__ b2, float* __restrict__ out)
{
    const int b = blockIdx.z;
    const float* Aq = q + (size_t)b * Sn * Dn;
    const float* Bk = k + (size_t)b * Sn * Dn;
    const float* Ah = h + (size_t)b * Sn * Hn;
    float* C = out + (size_t)b * Sn * Sn;

    __shared__ float As[2][16][APAD];
    __shared__ float Bs[2][16][APAD];

    const int tid = threadIdx.x;
    const int bm = blockIdx.y * 128;
    const int bn = blockIdx.x * 128;
    const int tx = tid & 15;
    const int ty = tid >> 4;

    const int row0 = tid >> 2;
    const int row1 = row0 + 64;
    const int kq   = (tid & 3) * 4;

    float acc[8][8];
#pragma unroll
    for (int i = 0; i < 8; ++i)
#pragma unroll
        for (int j = 0; j < 8; ++j) acc[i][j] = 0.f;

    // chunks 0..63: K = D over q/k ; chunks 64..67: K = H over h/w2t
    const int NCH = (Dn >> 4) + (Hn >> 4);   // 68

#define E_LOAD(t, a0, a1, b0, b1)                                               \
    if ((t) < (Dn >> 4)) {                                                      \
        const int k0 = (t) << 4;                                                \
        a0 = *(const float4*)(Aq + (size_t)(bm + row0) * Dn + k0 + kq);         \
        a1 = *(const float4*)(Aq + (size_t)(bm + row1) * Dn + k0 + kq);         \
        b0 = *(const float4*)(Bk + (size_t)(bn + row0) * Dn + k0 + kq);         \
        b1 = *(const float4*)(Bk + (size_t)(bn + row1) * Dn + k0 + kq);         \
    } else {                                                                    \
        const int k0 = ((t) - (Dn >> 4)) << 4;                                  \
        a0 = *(const float4*)(Ah  + (size_t)(bm + row0) * Hn + k0 + kq);        \
        a1 = *(const float4*)(Ah  + (size_t)(bm + row1) * Hn + k0 + kq);        \
        b0 = *(const float4*)(w2t + (size_t)(bn + row0) * Hn + k0 + kq);        \
        b1 = *(const float4*)(w2t + (size_t)(bn + row1) * Hn + k0 + kq);        \
    }

    {
        float4 a0, a1, b0, b1;
        E_LOAD(0, a0, a1, b0, b1);
        STORE_A_TRANS(As[0], a0, row0, kq);
        STORE_A_TRANS(As[0], a1, row1, kq);
        STORE_A_TRANS(Bs[0], b0, row0, kq);
        STORE_A_TRANS(Bs[0], b1, row1, kq);
    }
    __syncthreads();

    for (int t = 0; t < NCH; ++t) {
        const int buf = t & 1;
        float4 a0, a1, b0, b1;
        const bool more = (t + 1 < NCH);
        if (more) { E_LOAD(t + 1, a0, a1, b0, b1); }
        COMPUTE_CHUNK(As[buf], Bs[buf]);
        if (more) {
            const int nb = buf ^ 1;
            STORE_A_TRANS(As[nb], a0, row0, kq);
            STORE_A_TRANS(As[nb], a1, row1, kq);
            STORE_A_TRANS(Bs[nb], b0, row0, kq);
            STORE_A_TRANS(Bs[nb], b1, row1, kq);
            __syncthreads();
        }
    }
#undef E_LOAD

#pragma unroll
    for (int i = 0; i < 8; ++i) {
        const int row = bm + ty * 8 + i;
        const int col = bn + tx * 8;
#pragma unroll
        for (int hh = 0; hh < 2; ++hh) {
            float4 v  = *(float4*)&acc[i][hh * 4];
            const float4 bi = *(const float4*)(b2 + col + hh * 4);
            v.x += bi.x; v.y += bi.y; v.z += bi.z; v.w += bi.w;
            *(float4*)(C + (size_t)row * Sn + col + hh * 4) = v;
        }
    }
}

// ---------------- w2 [H,S] -> w2t [S,H] --------------------------------------
__global__ void transpose_w2(const float* __restrict__ w2, float* __restrict__ w2t)
{
    const int i = blockIdx.x * 256 + threadIdx.x;
    if (i < Sn * Hn) {
        const int t = i / Hn;
        const int e = i % Hn;
        w2t[i] = w2[e * Sn + t];
    }
}

// ---------------- row softmax: logits -> dst (may differ from src) -----------
__global__ void __launch_bounds__(256)
softmax_kernel(const float* __restrict__ logits, float* __restrict__ dst)
{
    const size_t row = blockIdx.x;
    const float* rp = logits + row * Sn;
    float* wp = dst + row * Sn;
    const int tid = threadIdx.x;

    __shared__ float sd[8];

    float v[8];
    float mx = -CUDART_INF_F;
#pragma unroll
    for (int j = 0; j < 8; ++j) {
        v[j] = rp[tid + 256 * j];
        mx = fmaxf(mx, v[j]);
    }
#pragma unroll
    for (int o = 16; o; o >>= 1) mx = fmaxf(mx, __shfl_xor_sync(0xffffffffu, mx, o));
    if ((tid & 31) == 0) sd[tid >> 5] = mx;
    __syncthreads();
    if (tid < 32) {
        float x = (tid < 8) ? sd[tid] : -CUDART_INF_F;
#pragma unroll
        for (int o = 4; o; o >>= 1) x = fmaxf(x, __shfl_xor_sync(0xffffffffu, x, o));
        if (tid == 0) sd[0] = x;
    }
    __syncthreads();
    mx = sd[0];
    __syncthreads();

    float s = 0.f;
#pragma unroll
    for (int j = 0; j < 8; ++j) {
        v[j] = __expf(v[j] - mx);
        s += v[j];
    }
#pragma unroll
    for (int o = 16; o; o >>= 1) s += __shfl_xor_sync(0xffffffffu, s, o);
    if ((tid & 31) == 0) sd[tid >> 5] = s;
    __syncthreads();
    if (tid < 32) {
        float x = (tid < 8) ? sd[tid] : 0.f;
#pragma unroll
        for (int o = 4; o; o >>= 1) x += __shfl_xor_sync(0xffffffffu, x, o);
        if (tid == 0) sd[0] = x;
    }
    __syncthreads();
    const float inv = 1.f / sd[0];

#pragma unroll
    for (int j = 0; j < 8; ++j)
        wp[tid + 256 * j] = v[j] * inv;
}

// ---------------- launch ------------------------------------------------------
extern "C" void kernel_launch(void* const* d_in, const int* in_sizes, int n_in,
                              void* d_out_v, int out_size)
{
    (void)in_sizes; (void)n_in;
    const float* query = (const float*)d_in[0];
    const float* key   = (const float*)d_in[1];
    const float* value = (const float*)d_in[2];
    const float* w1    = (const float*)d_in[3];
    const float* b1    = (const float*)d_in[4];
    const float* w2    = (const float*)d_in[5];
    const float* b2    = (const float*)d_in[6];
    const float* wq    = (const float*)d_in[7];
    const float* bq    = (const float*)d_in[8];
    const float* wk    = (const float*)d_in[9];
    const float* bk    = (const float*)d_in[10];
    float* d_out = (float*)d_out_v;

    float *hbuf, *qbuf, *kbuf, *logits, *w2t;
    cudaGetSymbolAddress((void**)&hbuf,   g_h);
    cudaGetSymbolAddress((void**)&qbuf,   g_q);
    cudaGetSymbolAddress((void**)&kbuf,   g_k);
    cudaGetSymbolAddress((void**)&logits, g_logits);
    cudaGetSymbolAddress((void**)&w2t,    g_w2t);

    const long long BSD = (long long)Bn * Sn * Dn;  //  33,554,432
    const long long BSS = (long long)Bn * Sn * Sn;  //  67,108,864

    float* out_ptr  = nullptr;
    float* attn_ptr = nullptr;
    if ((long long)out_size == BSD + BSS) { out_ptr = d_out; attn_ptr = d_out + BSD; }
    else if ((long long)out_size == BSS)  { attn_ptr = d_out; }
    else                                  { out_ptr = d_out; }

    const int M = Bn * Sn;  // 32768

    // h = relu(query @ w1 + b1)            [M, 64]
    sgemm_nn<true, true><<<dim3(1, M / 128, 1), 256>>>(
        query, w1, b1, hbuf, M, Hn, Dn, 0, 0, 0);

    // q = query @ wq + bq                  [M, 1024]
    sgemm_nn<false, true><<<dim3(Dn / 128, M / 128, 1), 256>>>(
        query, wq, bq, qbuf, M, Dn, Dn, 0, 0, 0);

    // k = key @ wk + bk                    [M, 1024]
    sgemm_nn<false, true><<<dim3(Dn / 128, M / 128, 1), 256>>>(
        key, wk, bk, kbuf, M, Dn, Dn, 0, 0, 0);

    // w2t = w2^T                           [S, H]
    transpose_w2<<<(Sn * Hn + 255) / 256, 256>>>(w2, w2t);

    // logits = q@k^T + h@w2t^T + b2        [B, S, S]
    energy_kernel<<<dim3(Sn / 128, Sn / 128, Bn), 256>>>(
        qbuf, kbuf, hbuf, w2t, b2, logits);

    // attention = softmax(logits); write straight to its final destination
    float* attn_final = attn_ptr ? attn_ptr : logits;
    softmax_kernel<<<Bn * Sn, 256>>>(logits, attn_final);

    // out = attention @ value              [B, S, D]
    if (out_ptr) {
        sgemm_nn<false, false><<<dim3(Dn / 128, Sn / 128, Bn), 256>>>(
            attn_final, value, nullptr, out_ptr, Sn, Dn, Sn,
            (long long)Sn * Sn, (long long)Sn * Dn, (long long)Sn * Dn);
    }
}

// round 3
// speedup vs baseline: 1.4988x; 1.4988x over previous
#include <cuda_runtime.h>
#include <math_constants.h>

#define Bn 16
#define Sn 2048
#define Dn 1024
#define Hn 64

#define APAD 132   // padded k-major tile row stride (16B aligned, conflict-free stores)

// ---------------- scratch (device globals; no allocations allowed) ----------
__device__ float g_h[(size_t)Bn * Sn * Hn];        //   8 MB  relu(query@w1+b1)
__device__ float g_q[(size_t)Bn * Sn * Dn];        // 134 MB  query proj
__device__ float g_k[(size_t)Bn * Sn * Dn];        // 134 MB  key proj
__device__ float g_logits[(size_t)Bn * Sn * Sn];   // 256 MB  logits
__device__ float g_w2t[Sn * Hn];                   // 512 KB  w2 transposed [S,H]

// ---------------- 8-deep fragment compute over one k-chunk -------------------
#define COMPUTE_CHUNK8(AS, BS)                                                 \
    _Pragma("unroll")                                                          \
    for (int kk = 0; kk < 8; ++kk) {                                           \
        float a[8], bb[8];                                                     \
        *(float4*)&a[0]  = *(const float4*)&AS[kk][ty * 8];                    \
        *(float4*)&a[4]  = *(const float4*)&AS[kk][ty * 8 + 4];                \
        *(float4*)&bb[0] = *(const float4*)&BS[kk][tx * 8];                    \
        *(float4*)&bb[4] = *(const float4*)&BS[kk][tx * 8 + 4];                \
        _Pragma("unroll") for (int i = 0; i < 8; ++i)                          \
            _Pragma("unroll") for (int j = 0; j < 8; ++j)                      \
                acc[i][j] += a[i] * bb[j];                                     \
    }

#define STORE_TRANS(DST, V, ROW, KQ)                                           \
    DST[(KQ) + 0][ROW] = (V).x;  DST[(KQ) + 1][ROW] = (V).y;                   \
    DST[(KQ) + 2][ROW] = (V).z;  DST[(KQ) + 3][ROW] = (V).w;

// ---------------- double-buffered 128x128x8 SGEMM (NN), bias/relu -----------
template <bool RELU, bool BIAS>
__global__ void __launch_bounds__(256, 2)
sgemm_nn(const float* __restrict__ A, const float* __restrict__ B,
         const float* __restrict__ bias, float* __restrict__ C,
         int M, int N, int K,
         long long strideA, long long strideB, long long strideC)
{
    A += (size_t)blockIdx.z * strideA;
    B += (size_t)blockIdx.z * strideB;
    C += (size_t)blockIdx.z * strideC;

    __shared__ float As[2][8][APAD];
    __shared__ float Bs[2][8][128];

    const int tid = threadIdx.x;
    const int bm = blockIdx.y * 128;
    const int bn = blockIdx.x * 128;
    const int tx = tid & 15;
    const int ty = tid >> 4;

    // A tile: 128 rows x 8 k = 256 float4 -> one per thread
    const int arow = tid >> 1;
    const int akq  = (tid & 1) * 4;
    // B tile: 8 rows x 128 cols = 256 float4 -> one per thread
    const int brow = tid >> 5;
    const int bcol = (tid & 31) * 4;
    const bool bok = (bn + bcol) < N;

    float acc[8][8];
#pragma unroll
    for (int i = 0; i < 8; ++i)
#pragma unroll
        for (int j = 0; j < 8; ++j) acc[i][j] = 0.f;

    const int nchunk = K >> 3;
    const float4 z4 = make_float4(0.f, 0.f, 0.f, 0.f);

    {   // preload chunk 0 into buffer 0
        float4 av = *(const float4*)(A + (size_t)(bm + arow) * K + akq);
        float4 bv = bok ? *(const float4*)(B + (size_t)brow * N + bn + bcol) : z4;
        STORE_TRANS(As[0], av, arow, akq);
        *(float4*)&Bs[0][brow][bcol] = bv;
    }
    __syncthreads();

    for (int t = 0; t < nchunk; ++t) {
        const int buf = t & 1;
        const bool more = (t + 1 < nchunk);
        float4 av, bv;
        if (more) {   // issue next chunk's global loads before compute
            const int k0 = (t + 1) << 3;
            av = *(const float4*)(A + (size_t)(bm + arow) * K + k0 + akq);
            bv = bok ? *(const float4*)(B + (size_t)(k0 + brow) * N + bn + bcol) : z4;
        }
        COMPUTE_CHUNK8(As[buf], Bs[buf]);
        if (more) {
            const int nb = buf ^ 1;
            STORE_TRANS(As[nb], av, arow, akq);
            *(float4*)&Bs[nb][brow][bcol] = bv;
            __syncthreads();
        }
    }

#pragma unroll
    for (int i = 0; i < 8; ++i) {
        const int row = bm + ty * 8 + i;
        const int col = bn + tx * 8;
#pragma unroll
        for (int h = 0; h < 2; ++h) {
            if (col + h * 4 < N) {
                float4 v = *(float4*)&acc[i][h * 4];
                if (BIAS) {
                    const float4 bi = *(const float4*)(bias + col + h * 4);
                    v.x += bi.x; v.y += bi.y; v.z += bi.z; v.w += bi.w;
                }
                if (RELU) {
                    v.x = fmaxf(v.x, 0.f); v.y = fmaxf(v.y, 0.f);
                    v.z = fmaxf(v.z, 0.f); v.w = fmaxf(v.w, 0.f);
                }
                *(float4*)(C + (size_t)row * N + col + h * 4) = v;
            }
        }
    }
}

// ---------------- energy: logits = q@k^T + h@w2t^T + b2 (NT, fused) ---------
__global__ void __launch_bounds__(256, 2)
energy_kernel(const float* __restrict__ q, const float* __restrict__ k,
              const float* __restrict__ h, const float* __restrict__ w2t,
              const float* __restrict__ b2, float* __restrict__ out)
{
    const int b = blockIdx.z;
    const float* Aq = q + (size_t)b * Sn * Dn;
    const float* Bk = k + (size_t)b * Sn * Dn;
    const float* Ah = h + (size_t)b * Sn * Hn;
    float* C = out + (size_t)b * Sn * Sn;

    __shared__ float As[2][8][APAD];
    __shared__ float Bs[2][8][APAD];

    const int tid = threadIdx.x;
    const int bm = blockIdx.y * 128;
    const int bn = blockIdx.x * 128;
    const int tx = tid & 15;
    const int ty = tid >> 4;

    const int lrow = tid >> 1;
    const int lkq  = (tid & 1) * 4;

    float acc[8][8];
#pragma unroll
    for (int i = 0; i < 8; ++i)
#pragma unroll
        for (int j = 0; j < 8; ++j) acc[i][j] = 0.f;

    // chunks 0..127: K = D over q/k^T ; chunks 128..135: K = H over h/w2t^T
    const int NCH = (Dn >> 3) + (Hn >> 3);   // 136

#define E_LOAD(t, av, bv)                                                       \
    if ((t) < (Dn >> 3)) {                                                      \
        const int k0 = (t) << 3;                                                \
        av = *(const float4*)(Aq + (size_t)(bm + lrow) * Dn + k0 + lkq);        \
        bv = *(const float4*)(Bk + (size_t)(bn + lrow) * Dn + k0 + lkq);        \
    } else {                                                                    \
        const int k0 = ((t) - (Dn >> 3)) << 3;                                  \
        av = *(const float4*)(Ah  + (size_t)(bm + lrow) * Hn + k0 + lkq);       \
        bv = *(const float4*)(w2t + (size_t)(bn + lrow) * Hn + k0 + lkq);       \
    }

    {
        float4 av, bv;
        E_LOAD(0, av, bv);
        STORE_TRANS(As[0], av, lrow, lkq);
        STORE_TRANS(Bs[0], bv, lrow, lkq);
    }
    __syncthreads();

    for (int t = 0; t < NCH; ++t) {
        const int buf = t & 1;
        const bool more = (t + 1 < NCH);
        float4 av, bv;
        if (more) { E_LOAD(t + 1, av, bv); }
        COMPUTE_CHUNK8(As[buf], Bs[buf]);
        if (more) {
            const int nb = buf ^ 1;
            STORE_TRANS(As[nb], av, lrow, lkq);
            STORE_TRANS(Bs[nb], bv, lrow, lkq);
            __syncthreads();
        }
    }
#undef E_LOAD

#pragma unroll
    for (int i = 0; i < 8; ++i) {
        const int row = bm + ty * 8 + i;
        const int col = bn + tx * 8;
#pragma unroll
        for (int hh = 0; hh < 2; ++hh) {
            float4 v  = *(float4*)&acc[i][hh * 4];
            const float4 bi = *(const float4*)(b2 + col + hh * 4);
            v.x += bi.x; v.y += bi.y; v.z += bi.z; v.w += bi.w;
            *(float4*)(C + (size_t)row * Sn + col + hh * 4) = v;
        }
    }
}

// ---------------- w2 [H,S] -> w2t [S,H] --------------------------------------
__global__ void transpose_w2(const float* __restrict__ w2, float* __restrict__ w2t)
{
    const int i = blockIdx.x * 256 + threadIdx.x;
    if (i < Sn * Hn) {
        const int t = i / Hn;
        const int e = i % Hn;
        w2t[i] = w2[e * Sn + t];
    }
}

// ---------------- row softmax: src -> dst ------------------------------------
__global__ void __launch_bounds__(256)
softmax_kernel(const float* __restrict__ logits, float* __restrict__ dst)
{
    const size_t row = blockIdx.x;
    const float* rp = logits + row * Sn;
    float* wp = dst + row * Sn;
    const int tid = threadIdx.x;

    __shared__ float sd[8];

    float v[8];
    float mx = -CUDART_INF_F;
#pragma unroll
    for (int j = 0; j < 8; ++j) {
        v[j] = rp[tid + 256 * j];
        mx = fmaxf(mx, v[j]);
    }
#pragma unroll
    for (int o = 16; o; o >>= 1) mx = fmaxf(mx, __shfl_xor_sync(0xffffffffu, mx, o));
    if ((tid & 31) == 0) sd[tid >> 5] = mx;
    __syncthreads();
    if (tid < 32) {
        float x = (tid < 8) ? sd[tid] : -CUDART_INF_F;
#pragma unroll
        for (int o = 4; o; o >>= 1) x = fmaxf(x, __shfl_xor_sync(0xffffffffu, x, o));
        if (tid == 0) sd[0] = x;
    }
    __syncthreads();
    mx = sd[0];
    __syncthreads();

    float s = 0.f;
#pragma unroll
    for (int j = 0; j < 8; ++j) {
        v[j] = __expf(v[j] - mx);
        s += v[j];
    }
#pragma unroll
    for (int o = 16; o; o >>= 1) s += __shfl_xor_sync(0xffffffffu, s, o);
    if ((tid & 31) == 0) sd[tid >> 5] = s;
    __syncthreads();
    if (tid < 32) {
        float x = (tid < 8) ? sd[tid] : 0.f;
#pragma unroll
        for (int o = 4; o; o >>= 1) x += __shfl_xor_sync(0xffffffffu, x, o);
        if (tid == 0) sd[0] = x;
    }
    __syncthreads();
    const float inv = 1.f / sd[0];

#pragma unroll
    for (int j = 0; j < 8; ++j)
        wp[tid + 256 * j] = v[j] * inv;
}

// ---------------- launch ------------------------------------------------------
extern "C" void kernel_launch(void* const* d_in, const int* in_sizes, int n_in,
                              void* d_out_v, int out_size)
{
    (void)in_sizes; (void)n_in;
    const float* query = (const float*)d_in[0];
    const float* key   = (const float*)d_in[1];
    const float* value = (const float*)d_in[2];
    const float* w1    = (const float*)d_in[3];
    const float* b1    = (const float*)d_in[4];
    const float* w2    = (const float*)d_in[5];
    const float* b2    = (const float*)d_in[6];
    const float* wq    = (const float*)d_in[7];
    const float* bq    = (const float*)d_in[8];
    const float* wk    = (const float*)d_in[9];
    const float* bk    = (const float*)d_in[10];
    float* d_out = (float*)d_out_v;

    float *hbuf, *qbuf, *kbuf, *logits, *w2t;
    cudaGetSymbolAddress((void**)&hbuf,   g_h);
    cudaGetSymbolAddress((void**)&qbuf,   g_q);
    cudaGetSymbolAddress((void**)&kbuf,   g_k);
    cudaGetSymbolAddress((void**)&logits, g_logits);
    cudaGetSymbolAddress((void**)&w2t,    g_w2t);

    const long long BSD = (long long)Bn * Sn * Dn;  //  33,554,432
    const long long BSS = (long long)Bn * Sn * Sn;  //  67,108,864

    float* out_ptr  = nullptr;
    float* attn_ptr = nullptr;
    if ((long long)out_size == BSD + BSS) { out_ptr = d_out; attn_ptr = d_out + BSD; }
    else if ((long long)out_size == BSS)  { attn_ptr = d_out; }
    else                                  { out_ptr = d_out; }

    const int M = Bn * Sn;  // 32768

    // h = relu(query @ w1 + b1)            [M, 64]
    sgemm_nn<true, true><<<dim3(1, M / 128, 1), 256>>>(
        query, w1, b1, hbuf, M, Hn, Dn, 0, 0, 0);

    // q = query @ wq + bq                  [M, 1024]
    sgemm_nn<false, true><<<dim3(Dn / 128, M / 128, 1), 256>>>(
        query, wq, bq, qbuf, M, Dn, Dn, 0, 0, 0);

    // k = key @ wk + bk                    [M, 1024]
    sgemm_nn<false, true><<<dim3(Dn / 128, M / 128, 1), 256>>>(
        key, wk, bk, kbuf, M, Dn, Dn, 0, 0, 0);

    // w2t = w2^T                           [S, H]
    transpose_w2<<<(Sn * Hn + 255) / 256, 256>>>(w2, w2t);

    // logits = q@k^T + h@w2t^T + b2        [B, S, S]
    energy_kernel<<<dim3(Sn / 128, Sn / 128, Bn), 256>>>(
        qbuf, kbuf, hbuf, w2t, b2, logits);

    // attention = softmax(logits); write straight to its final destination
    float* attn_final = attn_ptr ? attn_ptr : logits;
    softmax_kernel<<<Bn * Sn, 256>>>(logits, attn_final);

    // out = attention @ value              [B, S, D]
    if (out_ptr) {
        sgemm_nn<false, false><<<dim3(Dn / 128, Sn / 128, Bn), 256>>>(
            attn_final, value, nullptr, out_ptr, Sn, Dn, Sn,
            (long long)Sn * Sn, (long long)Sn * Dn, (long long)Sn * Dn);
    }
}

// round 4
// speedup vs baseline: 1.7767x; 1.1854x over previous
#include <cuda_runtime.h>
#include <math_constants.h>
#include <cstdint>

#define Bn 16
#define Sn 2048
#define Dn 1024
#define Hn 64

// ---------------- scratch (device globals; no allocations allowed) ----------
__device__ float g_h[(size_t)Bn * Sn * Hn];        //   8 MB  relu(query@w1+b1)
__device__ float g_q[(size_t)Bn * Sn * Dn];        // 134 MB  query proj
__device__ float g_k[(size_t)Bn * Sn * Dn];        // 134 MB  key proj
__device__ float g_logits[(size_t)Bn * Sn * Sn];   // 256 MB  logits
__device__ float g_w2t[Sn * Hn];                   // 512 KB  w2^T  [S,H]
__device__ float g_wqt[Dn * Dn];                   //   4 MB  wq^T  [N,K]
__device__ float g_wkt[Dn * Dn];                   //   4 MB  wk^T  [N,K]
__device__ float g_vt[(size_t)Bn * Dn * Sn];       // 134 MB  value^T [B,D,S]

// ---------------- tf32 helpers ----------------------------------------------
__device__ __forceinline__ uint32_t f2tf32(float x) {
    uint32_t r;
    asm("cvt.rna.tf32.f32 %0, %1;" : "=r"(r) : "f"(x));
    return r;
}

__device__ __forceinline__ void mma_tf32(float4& d,
                                         uint32_t a0, uint32_t a1, uint32_t a2, uint32_t a3,
                                         uint32_t b0, uint32_t b1) {
    asm volatile(
        "mma.sync.aligned.m16n8k8.row.col.f32.tf32.tf32.f32 "
        "{%0,%1,%2,%3}, {%4,%5,%6,%7}, {%8,%9}, {%0,%1,%2,%3};"
        : "+f"(d.x), "+f"(d.y), "+f"(d.z), "+f"(d.w)
        : "r"(a0), "r"(a1), "r"(a2), "r"(a3), "r"(b0), "r"(b1));
}

__device__ __forceinline__ void ldsm_x4(uint32_t& r0, uint32_t& r1, uint32_t& r2, uint32_t& r3,
                                        const float* p) {
    uint32_t addr = (uint32_t)__cvta_generic_to_shared(p);
    asm volatile("ldmatrix.sync.aligned.m8n8.x4.shared.b16 {%0,%1,%2,%3}, [%4];"
                 : "=r"(r0), "=r"(r1), "=r"(r2), "=r"(r3) : "r"(addr));
}

// =============================================================================
// tf32 3x-split NT GEMM: C[M,N] (+bias) = A[M,K] * B[N,K]^T
// optional fused second phase: += A2[M,K2] * B2[N,K2]^T
// CTA tile 128x128, warp tile 64x32, BK=16, double-buffered smem.
// All dims used here are multiples of the tile sizes (no guards).
// =============================================================================
template <bool PHASE2, bool BIAS>
__global__ void __launch_bounds__(256)
tf32_nt(const float* __restrict__ A, const float* __restrict__ Bm,
        const float* __restrict__ A2, const float* __restrict__ B2,
        const float* __restrict__ bias, float* __restrict__ C,
        int ldc, int K1, int lda, int ldb, int K2, int lda2, int ldb2,
        long long sA, long long sB, long long sC, long long sA2)
{
    A  += (size_t)blockIdx.z * sA;
    Bm += (size_t)blockIdx.z * sB;
    C  += (size_t)blockIdx.z * sC;
    if (PHASE2) A2 += (size_t)blockIdx.z * sA2;

    __shared__ float As[2][128][20];   // [row][k], stride 20 -> conflict-free LDSM
    __shared__ float Bs[2][128][20];

    const int tid  = threadIdx.x;
    const int lane = tid & 31;
    const int wid  = tid >> 5;
    const int wm   = (wid & 1) * 64;
    const int wn   = (wid >> 1) * 32;
    const int bm   = blockIdx.y * 128;
    const int bn   = blockIdx.x * 128;

    // tile loader: 128 rows x 16 k, each thread: row tid>>1, k half (tid&1)*8
    const int l_row = tid >> 1;
    const int l_k   = (tid & 1) * 8;

    // ldmatrix per-lane source coords
    const int a_r = (lane & 7) + ((lane >> 3) & 1) * 8;   // A: q0/q2 rows 0-7, q1/q3 +8
    const int a_c = (lane >> 4) * 4;                      // A: q2/q3 k+4
    const int b_r = (lane & 7) + ((lane >> 4) & 1) * 8;   // B: q2/q3 n+8
    const int b_c = ((lane >> 3) & 1) * 4;                // B: q1/q3 k+4

    float4 acc[4][4];
#pragma unroll
    for (int i = 0; i < 4; ++i)
#pragma unroll
        for (int j = 0; j < 4; ++j) acc[i][j] = make_float4(0.f, 0.f, 0.f, 0.f);

    const int nch1 = K1 >> 4;
    const int nch  = nch1 + (PHASE2 ? (K2 >> 4) : 0);

    float4 av0, av1, bv0, bv1;

#define G_LOAD(T)                                                                  \
    {                                                                              \
        const int _t = (T);                                                        \
        if (!PHASE2 || _t < nch1) {                                                \
            const float* ap = A  + (size_t)(bm + l_row) * lda + _t * 16 + l_k;     \
            const float* bp = Bm + (size_t)(bn + l_row) * ldb + _t * 16 + l_k;     \
            av0 = *(const float4*)ap;       av1 = *(const float4*)(ap + 4);        \
            bv0 = *(const float4*)bp;       bv1 = *(const float4*)(bp + 4);        \
        } else {                                                                   \
            const int k0 = (_t - nch1) * 16;                                       \
            const float* ap = A2 + (size_t)(bm + l_row) * lda2 + k0 + l_k;         \
            const float* bp = B2 + (size_t)(bn + l_row) * ldb2 + k0 + l_k;         \
            av0 = *(const float4*)ap;       av1 = *(const float4*)(ap + 4);        \
            bv0 = *(const float4*)bp;       bv1 = *(const float4*)(bp + 4);        \
        }                                                                          \
    }

#define S_STORE(BUF)                                                               \
    *(float4*)&As[BUF][l_row][l_k]     = av0;                                      \
    *(float4*)&As[BUF][l_row][l_k + 4] = av1;                                      \
    *(float4*)&Bs[BUF][l_row][l_k]     = bv0;                                      \
    *(float4*)&Bs[BUF][l_row][l_k + 4] = bv1;

    G_LOAD(0);
    S_STORE(0);
    __syncthreads();

    for (int t = 0; t < nch; ++t) {
        const int buf = t & 1;
        const bool more = (t + 1 < nch);
        if (more) G_LOAD(t + 1);

#pragma unroll
        for (int kk = 0; kk < 2; ++kk) {
            const int kb = kk * 8;

            uint32_t Ar[4][4];
#pragma unroll
            for (int mi = 0; mi < 4; ++mi)
                ldsm_x4(Ar[mi][0], Ar[mi][1], Ar[mi][2], Ar[mi][3],
                        &As[buf][wm + mi * 16 + a_r][kb + a_c]);

            uint32_t Br[4][2];
#pragma unroll
            for (int p = 0; p < 2; ++p)
                ldsm_x4(Br[2 * p][0], Br[2 * p][1], Br[2 * p + 1][0], Br[2 * p + 1][1],
                        &Bs[buf][wn + p * 16 + b_r][kb + b_c]);

            // 3x tf32 split
            uint32_t Ahi[4][4], Alo[4][4], Bhi[4][2], Blo[4][2];
#pragma unroll
            for (int mi = 0; mi < 4; ++mi)
#pragma unroll
                for (int r = 0; r < 4; ++r) {
                    const float x = __uint_as_float(Ar[mi][r]);
                    const uint32_t hi = f2tf32(x);
                    Ahi[mi][r] = hi;
                    Alo[mi][r] = __float_as_uint(x - __uint_as_float(hi));
                }
#pragma unroll
            for (int ni = 0; ni < 4; ++ni)
#pragma unroll
                for (int r = 0; r < 2; ++r) {
                    const float x = __uint_as_float(Br[ni][r]);
                    const uint32_t hi = f2tf32(x);
                    Bhi[ni][r] = hi;
                    Blo[ni][r] = __float_as_uint(x - __uint_as_float(hi));
                }

#pragma unroll
            for (int mi = 0; mi < 4; ++mi)
#pragma unroll
                for (int ni = 0; ni < 4; ++ni) {
                    mma_tf32(acc[mi][ni], Alo[mi][0], Alo[mi][1], Alo[mi][2], Alo[mi][3],
                             Bhi[ni][0], Bhi[ni][1]);
                    mma_tf32(acc[mi][ni], Ahi[mi][0], Ahi[mi][1], Ahi[mi][2], Ahi[mi][3],
                             Blo[ni][0], Blo[ni][1]);
                    mma_tf32(acc[mi][ni], Ahi[mi][0], Ahi[mi][1], Ahi[mi][2], Ahi[mi][3],
                             Bhi[ni][0], Bhi[ni][1]);
                }
        }

        if (more) {
            S_STORE(buf ^ 1);
            __syncthreads();
        }
    }
#undef G_LOAD
#undef S_STORE

    // epilogue: c0,c1 -> (row, col..col+1); c2,c3 -> (row+8, col..col+1)
    const int er = lane >> 2;
    const int ec = (lane & 3) * 2;
#pragma unroll
    for (int mi = 0; mi < 4; ++mi) {
        const int row = bm + wm + mi * 16 + er;
#pragma unroll
        for (int ni = 0; ni < 4; ++ni) {
            const int col = bn + wn + ni * 8 + ec;
            float2 v0 = make_float2(acc[mi][ni].x, acc[mi][ni].y);
            float2 v1 = make_float2(acc[mi][ni].z, acc[mi][ni].w);
            if (BIAS) {
                const float2 bi = *(const float2*)(bias + col);
                v0.x += bi.x; v0.y += bi.y;
                v1.x += bi.x; v1.y += bi.y;
            }
            *(float2*)(C + (size_t)row * ldc + col)       = v0;
            *(float2*)(C + (size_t)(row + 8) * ldc + col) = v1;
        }
    }
}

// ---------------- generic 32x32 tiled transpose ------------------------------
__global__ void transpose_k(const float* __restrict__ in, float* __restrict__ out,
                            int R, int C, long long sIn, long long sOut)
{
    __shared__ float t[32][33];
    in  += (size_t)blockIdx.z * sIn;
    out += (size_t)blockIdx.z * sOut;
    const int r0 = blockIdx.y * 32, c0 = blockIdx.x * 32;
    const int x = threadIdx.x, y = threadIdx.y;
#pragma unroll
    for (int i = y; i < 32; i += 8)
        if (r0 + i < R && c0 + x < C) t[i][x] = in[(size_t)(r0 + i) * C + c0 + x];
    __syncthreads();
#pragma unroll
    for (int i = y; i < 32; i += 8)
        if (c0 + i < C && r0 + x < R) out[(size_t)(c0 + i) * R + r0 + x] = t[x][i];
}

// ---------------- FFMA SGEMM (kept for the small h = relu(q@w1+b1)) ---------
#define APAD 132
#define COMPUTE_CHUNK8(AS, BS)                                                 \
    _Pragma("unroll")                                                          \
    for (int kk = 0; kk < 8; ++kk) {                                           \
        float a[8], bb[8];                                                     \
        *(float4*)&a[0]  = *(const float4*)&AS[kk][ty * 8];                    \
        *(float4*)&a[4]  = *(const float4*)&AS[kk][ty * 8 + 4];                \
        *(float4*)&bb[0] = *(const float4*)&BS[kk][tx * 8];                    \
        *(float4*)&bb[4] = *(const float4*)&BS[kk][tx * 8 + 4];                \
        _Pragma("unroll") for (int i = 0; i < 8; ++i)                          \
            _Pragma("unroll") for (int j = 0; j < 8; ++j)                      \
                acc[i][j] += a[i] * bb[j];                                     \
    }
#define STORE_TRANS(DST, V, ROW, KQ)                                           \
    DST[(KQ) + 0][ROW] = (V).x;  DST[(KQ) + 1][ROW] = (V).y;                   \
    DST[(KQ) + 2][ROW] = (V).z;  DST[(KQ) + 3][ROW] = (V).w;

template <bool RELU, bool BIAS>
__global__ void __launch_bounds__(256, 2)
sgemm_nn(const float* __restrict__ A, const float* __restrict__ B,
         const float* __restrict__ bias, float* __restrict__ C,
         int M, int N, int K)
{
    __shared__ float As[2][8][APAD];
    __shared__ float Bs[2][8][128];

    const int tid = threadIdx.x;
    const int bm = blockIdx.y * 128;
    const int bn = blockIdx.x * 128;
    const int tx = tid & 15;
    const int ty = tid >> 4;

    const int arow = tid >> 1;
    const int akq  = (tid & 1) * 4;
    const int brow = tid >> 5;
    const int bcol = (tid & 31) * 4;
    const bool bok = (bn + bcol) < N;

    float acc[8][8];
#pragma unroll
    for (int i = 0; i < 8; ++i)
#pragma unroll
        for (int j = 0; j < 8; ++j) acc[i][j] = 0.f;

    const int nchunk = K >> 3;
    const float4 z4 = make_float4(0.f, 0.f, 0.f, 0.f);

    {
        float4 av = *(const float4*)(A + (size_t)(bm + arow) * K + akq);
        float4 bv = bok ? *(const float4*)(B + (size_t)brow * N + bn + bcol) : z4;
        STORE_TRANS(As[0], av, arow, akq);
        *(float4*)&Bs[0][brow][bcol] = bv;
    }
    __syncthreads();

    for (int t = 0; t < nchunk; ++t) {
        const int buf = t & 1;
        const bool more = (t + 1 < nchunk);
        float4 av, bv;
        if (more) {
            const int k0 = (t + 1) << 3;
            av = *(const float4*)(A + (size_t)(bm + arow) * K + k0 + akq);
            bv = bok ? *(const float4*)(B + (size_t)(k0 + brow) * N + bn + bcol) : z4;
        }
        COMPUTE_CHUNK8(As[buf], Bs[buf]);
        if (more) {
            const int nb = buf ^ 1;
            STORE_TRANS(As[nb], av, arow, akq);
            *(float4*)&Bs[nb][brow][bcol] = bv;
            __syncthreads();
        }
    }

#pragma unroll
    for (int i = 0; i < 8; ++i) {
        const int row = bm + ty * 8 + i;
        const int col = bn + tx * 8;
#pragma unroll
        for (int h = 0; h < 2; ++h) {
            if (col + h * 4 < N) {
                float4 v = *(float4*)&acc[i][h * 4];
                if (BIAS) {
                    const float4 bi = *(const float4*)(bias + col + h * 4);
                    v.x += bi.x; v.y += bi.y; v.z += bi.z; v.w += bi.w;
                }
                if (RELU) {
                    v.x = fmaxf(v.x, 0.f); v.y = fmaxf(v.y, 0.f);
                    v.z = fmaxf(v.z, 0.f); v.w = fmaxf(v.w, 0.f);
                }
                *(float4*)(C + (size_t)row * N + col + h * 4) = v;
            }
        }
    }
}

// ---------------- row softmax: src -> dst ------------------------------------
__global__ void __launch_bounds__(256)
softmax_kernel(const float* __restrict__ logits, float* __restrict__ dst)
{
    const size_t row = blockIdx.x;
    const float* rp = logits + row * Sn;
    float* wp = dst + row * Sn;
    const int tid = threadIdx.x;

    __shared__ float sd[8];

    float v[8];
    float mx = -CUDART_INF_F;
#pragma unroll
    for (int j = 0; j < 8; ++j) {
        v[j] = rp[tid + 256 * j];
        mx = fmaxf(mx, v[j]);
    }
#pragma unroll
    for (int o = 16; o; o >>= 1) mx = fmaxf(mx, __shfl_xor_sync(0xffffffffu, mx, o));
    if ((tid & 31) == 0) sd[tid >> 5] = mx;
    __syncthreads();
    if (tid < 32) {
        float x = (tid < 8) ? sd[tid] : -CUDART_INF_F;
#pragma unroll
        for (int o = 4; o; o >>= 1) x = fmaxf(x, __shfl_xor_sync(0xffffffffu, x, o));
        if (tid == 0) sd[0] = x;
    }
    __syncthreads();
    mx = sd[0];
    __syncthreads();

    float s = 0.f;
#pragma unroll
    for (int j = 0; j < 8; ++j) {
        v[j] = __expf(v[j] - mx);
        s += v[j];
    }
#pragma unroll
    for (int o = 16; o; o >>= 1) s += __shfl_xor_sync(0xffffffffu, s, o);
    if ((tid & 31) == 0) sd[tid >> 5] = s;
    __syncthreads();
    if (tid < 32) {
        float x = (tid < 8) ? sd[tid] : 0.f;
#pragma unroll
        for (int o = 4; o; o >>= 1) x += __shfl_xor_sync(0xffffffffu, x, o);
        if (tid == 0) sd[0] = x;
    }
    __syncthreads();
    const float inv = 1.f / sd[0];

#pragma unroll
    for (int j = 0; j < 8; ++j)
        wp[tid + 256 * j] = v[j] * inv;
}

// ---------------- launch ------------------------------------------------------
extern "C" void kernel_launch(void* const* d_in, const int* in_sizes, int n_in,
                              void* d_out_v, int out_size)
{
    (void)in_sizes; (void)n_in;
    const float* query = (const float*)d_in[0];
    const float* key   = (const float*)d_in[1];
    const float* value = (const float*)d_in[2];
    const float* w1    = (const float*)d_in[3];
    const float* b1    = (const float*)d_in[4];
    const float* w2    = (const float*)d_in[5];
    const float* b2    = (const float*)d_in[6];
    const float* wq    = (const float*)d_in[7];
    const float* bq    = (const float*)d_in[8];
    const float* wk    = (const float*)d_in[9];
    const float* bk    = (const float*)d_in[10];
    float* d_out = (float*)d_out_v;

    float *hbuf, *qbuf, *kbuf, *logits, *w2t, *wqt, *wkt, *vt;
    cudaGetSymbolAddress((void**)&hbuf,   g_h);
    cudaGetSymbolAddress((void**)&qbuf,   g_q);
    cudaGetSymbolAddress((void**)&kbuf,   g_k);
    cudaGetSymbolAddress((void**)&logits, g_logits);
    cudaGetSymbolAddress((void**)&w2t,    g_w2t);
    cudaGetSymbolAddress((void**)&wqt,    g_wqt);
    cudaGetSymbolAddress((void**)&wkt,    g_wkt);
    cudaGetSymbolAddress((void**)&vt,     g_vt);

    const long long BSD = (long long)Bn * Sn * Dn;
    const long long BSS = (long long)Bn * Sn * Sn;

    float* out_ptr  = nullptr;
    float* attn_ptr = nullptr;
    if ((long long)out_size == BSD + BSS) { out_ptr = d_out; attn_ptr = d_out + BSD; }
    else if ((long long)out_size == BSS)  { attn_ptr = d_out; }
    else                                  { out_ptr = d_out; }

    const int M = Bn * Sn;  // 32768

    // -- pre-transposes (make every big GEMM NT / k-contiguous) --
    transpose_k<<<dim3(Dn / 32, Dn / 32, 1), dim3(32, 8)>>>(wq, wqt, Dn, Dn, 0, 0);
    transpose_k<<<dim3(Dn / 32, Dn / 32, 1), dim3(32, 8)>>>(wk, wkt, Dn, Dn, 0, 0);
    transpose_k<<<dim3(Sn / 32, (Hn + 31) / 32, 1), dim3(32, 8)>>>(w2, w2t, Hn, Sn, 0, 0);
    transpose_k<<<dim3(Dn / 32, Sn / 32, Bn), dim3(32, 8)>>>(
        value, vt, Sn, Dn, (long long)Sn * Dn, (long long)Sn * Dn);

    // -- h = relu(query @ w1 + b1)   [M, 64]  (small; FFMA path) --
    sgemm_nn<true, true><<<dim3(1, M / 128, 1), 256>>>(query, w1, b1, hbuf, M, Hn, Dn);

    // -- q = query @ wqt^T + bq   [M, 1024] --
    tf32_nt<false, true><<<dim3(Dn / 128, M / 128, 1), 256>>>(
        query, wqt, nullptr, nullptr, bq, qbuf,
        Dn, Dn, Dn, Dn, 0, 0, 0, 0, 0, 0, 0);

    // -- k = key @ wkt^T + bk   [M, 1024] --
    tf32_nt<false, true><<<dim3(Dn / 128, M / 128, 1), 256>>>(
        key, wkt, nullptr, nullptr, bk, kbuf,
        Dn, Dn, Dn, Dn, 0, 0, 0, 0, 0, 0, 0);

    // -- logits = q@k^T + h@w2t^T + b2   [B, S, S] --
    tf32_nt<true, true><<<dim3(Sn / 128, Sn / 128, Bn), 256>>>(
        qbuf, kbuf, hbuf, w2t, b2, logits,
        Sn, Dn, Dn, Dn, Hn, Hn, Hn,
        (long long)Sn * Dn, (long long)Sn * Dn, (long long)Sn * Sn, (long long)Sn * Hn);

    // -- attention = softmax(logits) --
    float* attn_final = attn_ptr ? attn_ptr : logits;
    softmax_kernel<<<Bn * Sn, 256>>>(logits, attn_final);

    // -- out = attention @ vt^T   [B, S, D] --
    if (out_ptr) {
        tf32_nt<false, false><<<dim3(Dn / 128, Sn / 128, Bn), 256>>>(
            attn_final, vt, nullptr, nullptr, nullptr, out_ptr,
            Dn, Sn, Sn, Sn, 0, 0, 0,
            (long long)Sn * Sn, (long long)Dn * Sn, (long long)Sn * Dn, 0);
    }
}

// round 6
// speedup vs baseline: 3.1277x; 1.7604x over previous
#include <cuda_runtime.h>
#include <cuda_bf16.h>
#include <math_constants.h>
#include <cstdint>

#define Bn 16
#define Sn 2048
#define Dn 1024
#define Hn 64
#define Mn (Bn * Sn)   // 32768

typedef __nv_bfloat16 bf16;

// ---------------- scratch (device globals; no allocations allowed) ----------
__device__ __align__(16) bf16  g_queryh[(size_t)Mn * Dn], g_queryl[(size_t)Mn * Dn];
__device__ __align__(16) bf16  g_keyh[(size_t)Mn * Dn],   g_keyl[(size_t)Mn * Dn];
__device__ __align__(16) bf16  g_qh[(size_t)Mn * Dn],     g_ql[(size_t)Mn * Dn];
__device__ __align__(16) bf16  g_kh[(size_t)Mn * Dn],     g_kl[(size_t)Mn * Dn];
__device__ __align__(16) bf16  g_wqth[Dn * Dn], g_wqtl[Dn * Dn];
__device__ __align__(16) bf16  g_wkth[Dn * Dn], g_wktl[Dn * Dn];
__device__ __align__(16) bf16  g_w2th[Sn * Hn], g_w2tl[Sn * Hn];
__device__ __align__(16) bf16  g_hh[(size_t)Mn * Hn], g_hl[(size_t)Mn * Hn];
__device__ __align__(16) bf16  g_attnh[(size_t)Bn * Sn * Sn], g_attnl[(size_t)Bn * Sn * Sn];
__device__ __align__(16) bf16  g_vth[(size_t)Bn * Dn * Sn],   g_vtl[(size_t)Bn * Dn * Sn];
__device__ __align__(16) float g_hf[(size_t)Mn * Hn];
__device__ __align__(16) float g_logits[(size_t)Bn * Sn * Sn];

// ---------------- helpers -----------------------------------------------------
__device__ __forceinline__ void split_bf16(float x, bf16& hi, bf16& lo) {
    hi = __float2bfloat16_rn(x);
    lo = __float2bfloat16_rn(x - __bfloat162float(hi));
}

__device__ __forceinline__ void ldsm_x4(uint32_t& r0, uint32_t& r1, uint32_t& r2, uint32_t& r3,
                                        const void* p) {
    uint32_t addr = (uint32_t)__cvta_generic_to_shared(p);
    asm volatile("ldmatrix.sync.aligned.m8n8.x4.shared.b16 {%0,%1,%2,%3}, [%4];"
                 : "=r"(r0), "=r"(r1), "=r"(r2), "=r"(r3) : "r"(addr));
}

__device__ __forceinline__ void mma_bf16(float4& d, const uint32_t* a, const uint32_t* b) {
    asm volatile(
        "mma.sync.aligned.m16n8k16.row.col.f32.bf16.bf16.f32 "
        "{%0,%1,%2,%3}, {%4,%5,%6,%7}, {%8,%9}, {%0,%1,%2,%3};"
        : "+f"(d.x), "+f"(d.y), "+f"(d.z), "+f"(d.w)
        : "r"(a[0]), "r"(a[1]), "r"(a[2]), "r"(a[3]), "r"(b[0]), "r"(b[1]));
}

// =============================================================================
// bf16 3x-split NT GEMM: C[M,N] = (Ah+Al)[M,K] * ((Bh+Bl)[N,K])^T (+bias)
// optional fused phase2 += A2*B2^T ; output fp32 or split bf16 hi/lo
// CTA 128x128, warp 64x32, BK=32 bf16, double-buffered, ldmatrix + m16n8k16.
// =============================================================================
#define TSTR 40   // smem row stride in bf16 (80 B: 16B-aligned rows, conflict-free LDSM)

template <bool PHASE2, bool BIAS, bool SPLITOUT>
__global__ void __launch_bounds__(256)
bf16_nt(const bf16* __restrict__ Ah_g, const bf16* __restrict__ Al_g,
        const bf16* __restrict__ Bh_g, const bf16* __restrict__ Bl_g,
        const bf16* __restrict__ A2h,  const bf16* __restrict__ A2l,
        const bf16* __restrict__ B2h,  const bf16* __restrict__ B2l,
        const float* __restrict__ bias,
        float* __restrict__ C, bf16* __restrict__ Ch, bf16* __restrict__ Cl,
        int ldc, int K1, int lda, int ldb, int K2, int lda2, int ldb2,
        long long sA, long long sB, long long sC, long long sA2)
{
    Ah_g += (size_t)blockIdx.z * sA;  Al_g += (size_t)blockIdx.z * sA;
    Bh_g += (size_t)blockIdx.z * sB;  Bl_g += (size_t)blockIdx.z * sB;
    if (PHASE2) { A2h += (size_t)blockIdx.z * sA2; A2l += (size_t)blockIdx.z * sA2; }
    const size_t cof = (size_t)blockIdx.z * sC;

    // [buf][mat: 0=Ah 1=Al 2=Bh 3=Bl][row][k]
    __shared__ bf16 sm[2][4][128][TSTR];

    const int tid  = threadIdx.x;
    const int lane = tid & 31;
    const int wid  = tid >> 5;
    const int wm   = (wid & 1) * 64;
    const int wn   = (wid >> 1) * 32;
    const int bm   = blockIdx.y * 128;
    const int bn   = blockIdx.x * 128;

    // loader: per matrix, thread covers row tid>>1, 16 elements at (tid&1)*16
    const int l_row  = tid >> 1;
    const int l_half = (tid & 1) * 16;

    // ldmatrix lane source coords
    const int a_r = lane & 15;                             // A rows
    const int a_c = (lane >> 4) * 8;                       // A k-col (q2/q3 -> k+8)
    const int b_r = ((lane >> 4) & 1) * 8 + (lane & 7);    // B n-row
    const int b_c = ((lane >> 3) & 1) * 8;                 // B k-col

    float4 acc[4][4];
#pragma unroll
    for (int i = 0; i < 4; ++i)
#pragma unroll
        for (int j = 0; j < 4; ++j) acc[i][j] = make_float4(0.f, 0.f, 0.f, 0.f);

    const int nch1 = K1 >> 5;
    const int nch  = nch1 + (PHASE2 ? (K2 >> 5) : 0);

    uint4 v[4][2];

#define G_LOAD(T)                                                                   \
    {                                                                               \
        const int _t = (T);                                                         \
        const bf16 *pa_h, *pa_l, *pb_h, *pb_l;                                      \
        if (!PHASE2 || _t < nch1) {                                                 \
            const int k0 = _t * 32 + l_half;                                        \
            pa_h = Ah_g + (size_t)(bm + l_row) * lda + k0;                          \
            pa_l = Al_g + (size_t)(bm + l_row) * lda + k0;                          \
            pb_h = Bh_g + (size_t)(bn + l_row) * ldb + k0;                          \
            pb_l = Bl_g + (size_t)(bn + l_row) * ldb + k0;                          \
        } else {                                                                    \
            const int k0 = (_t - nch1) * 32 + l_half;                               \
            pa_h = A2h + (size_t)(bm + l_row) * lda2 + k0;                          \
            pa_l = A2l + (size_t)(bm + l_row) * lda2 + k0;                          \
            pb_h = B2h + (size_t)(bn + l_row) * ldb2 + k0;                          \
            pb_l = B2l + (size_t)(bn + l_row) * ldb2 + k0;                          \
        }                                                                           \
        v[0][0] = *(const uint4*)pa_h;  v[0][1] = *(const uint4*)(pa_h + 8);        \
        v[1][0] = *(const uint4*)pa_l;  v[1][1] = *(const uint4*)(pa_l + 8);        \
        v[2][0] = *(const uint4*)pb_h;  v[2][1] = *(const uint4*)(pb_h + 8);        \
        v[3][0] = *(const uint4*)pb_l;  v[3][1] = *(const uint4*)(pb_l + 8);        \
    }

#define S_STORE(BUF)                                                                \
    _Pragma("unroll")                                                               \
    for (int m = 0; m < 4; ++m) {                                                   \
        *(uint4*)&sm[BUF][m][l_row][l_half]     = v[m][0];                          \
        *(uint4*)&sm[BUF][m][l_row][l_half + 8] = v[m][1];                          \
    }

    G_LOAD(0);
    S_STORE(0);
    __syncthreads();

    for (int t = 0; t < nch; ++t) {
        const int buf = t & 1;
        const bool more = (t + 1 < nch);
        if (more) G_LOAD(t + 1);

#pragma unroll
        for (int kk = 0; kk < 2; ++kk) {
            const int kb = kk * 16;

            uint32_t ah[4][4], al[4][4], bh[4][2], bl[4][2];
#pragma unroll
            for (int mi = 0; mi < 4; ++mi) {
                ldsm_x4(ah[mi][0], ah[mi][1], ah[mi][2], ah[mi][3],
                        &sm[buf][0][wm + mi * 16 + a_r][kb + a_c]);
                ldsm_x4(al[mi][0], al[mi][1], al[mi][2], al[mi][3],
                        &sm[buf][1][wm + mi * 16 + a_r][kb + a_c]);
            }
#pragma unroll
            for (int p = 0; p < 2; ++p) {
                ldsm_x4(bh[2 * p][0], bh[2 * p][1], bh[2 * p + 1][0], bh[2 * p + 1][1],
                        &sm[buf][2][wn + p * 16 + b_r][kb + b_c]);
                ldsm_x4(bl[2 * p][0], bl[2 * p][1], bl[2 * p + 1][0], bl[2 * p + 1][1],
                        &sm[buf][3][wn + p * 16 + b_r][kb + b_c]);
            }

#pragma unroll
            for (int mi = 0; mi < 4; ++mi)
#pragma unroll
                for (int ni = 0; ni < 4; ++ni) {
                    mma_bf16(acc[mi][ni], ah[mi], bl[ni]);
                    mma_bf16(acc[mi][ni], al[mi], bh[ni]);
                    mma_bf16(acc[mi][ni], ah[mi], bh[ni]);
                }
        }

        if (more) {
            S_STORE(buf ^ 1);
            __syncthreads();
        }
    }
#undef G_LOAD
#undef S_STORE

    // epilogue: regs {x,y}->(row, col,col+1); {z,w}->(row+8, ...)
    const int er = lane >> 2;
    const int ec = (lane & 3) * 2;
#pragma unroll
    for (int mi = 0; mi < 4; ++mi) {
        const int row = bm + wm + mi * 16 + er;
#pragma unroll
        for (int ni = 0; ni < 4; ++ni) {
            const int col = bn + wn + ni * 8 + ec;
            float2 v0 = make_float2(acc[mi][ni].x, acc[mi][ni].y);
            float2 v1 = make_float2(acc[mi][ni].z, acc[mi][ni].w);
            if (BIAS) {
                const float2 bi = *(const float2*)(bias + col);
                v0.x += bi.x; v0.y += bi.y;
                v1.x += bi.x; v1.y += bi.y;
            }
            if (SPLITOUT) {
                __nv_bfloat162 h2, l2;
                split_bf16(v0.x, h2.x, l2.x);  split_bf16(v0.y, h2.y, l2.y);
                *(__nv_bfloat162*)(Ch + cof + (size_t)row * ldc + col) = h2;
                *(__nv_bfloat162*)(Cl + cof + (size_t)row * ldc + col) = l2;
                split_bf16(v1.x, h2.x, l2.x);  split_bf16(v1.y, h2.y, l2.y);
                *(__nv_bfloat162*)(Ch + cof + (size_t)(row + 8) * ldc + col) = h2;
                *(__nv_bfloat162*)(Cl + cof + (size_t)(row + 8) * ldc + col) = l2;
            } else {
                *(float2*)(C + cof + (size_t)row * ldc + col)       = v0;
                *(float2*)(C + cof + (size_t)(row + 8) * ldc + col) = v1;
            }
        }
    }
}

// ---------------- transpose fp32 -> split bf16 hi/lo -------------------------
__global__ void transpose_split(const float* __restrict__ in,
                                bf16* __restrict__ oh, bf16* __restrict__ ol,
                                int R, int C, long long sIn, long long sOut)
{
    __shared__ float t[32][33];
    in += (size_t)blockIdx.z * sIn;
    oh += (size_t)blockIdx.z * sOut;
    ol += (size_t)blockIdx.z * sOut;
    const int r0 = blockIdx.y * 32, c0 = blockIdx.x * 32;
    const int x = threadIdx.x, y = threadIdx.y;
#pragma unroll
    for (int i = y; i < 32; i += 8)
        if (r0 + i < R && c0 + x < C) t[i][x] = in[(size_t)(r0 + i) * C + c0 + x];
    __syncthreads();
#pragma unroll
    for (int i = y; i < 32; i += 8)
        if (c0 + i < C && r0 + x < R) {
            bf16 hi, lo;
            split_bf16(t[x][i], hi, lo);
            oh[(size_t)(c0 + i) * R + r0 + x] = hi;
            ol[(size_t)(c0 + i) * R + r0 + x] = lo;
        }
}

// ---------------- flat fp32 -> split bf16 hi/lo -------------------------------
__global__ void convert_split(const float* __restrict__ in,
                              bf16* __restrict__ oh, bf16* __restrict__ ol, int n4)
{
    const int i = blockIdx.x * 256 + threadIdx.x;
    if (i < n4) {
        const float4 f = ((const float4*)in)[i];
        __nv_bfloat162 h0, l0, h1, l1;
        split_bf16(f.x, h0.x, l0.x);  split_bf16(f.y, h0.y, l0.y);
        split_bf16(f.z, h1.x, l1.x);  split_bf16(f.w, h1.y, l1.y);
        ((__nv_bfloat162*)oh)[2 * i]     = h0;
        ((__nv_bfloat162*)oh)[2 * i + 1] = h1;
        ((__nv_bfloat162*)ol)[2 * i]     = l0;
        ((__nv_bfloat162*)ol)[2 * i + 1] = l1;
    }
}

// ---------------- FFMA SGEMM for h = relu(query@w1+b1) ------------------------
#define APAD 132
template <bool RELU, bool BIAS>
__global__ void __launch_bounds__(256, 2)
sgemm_nn(const float* __restrict__ A, const float* __restrict__ B,
         const float* __restrict__ bias, float* __restrict__ C,
         int M, int N, int K)
{
    __shared__ float As[2][8][APAD];
    __shared__ float Bs[2][8][128];

    const int tid = threadIdx.x;
    const int bm = blockIdx.y * 128;
    const int bn = blockIdx.x * 128;
    const int tx = tid & 15;
    const int ty = tid >> 4;

    const int arow = tid >> 1;
    const int akq  = (tid & 1) * 4;
    const int brow = tid >> 5;
    const int bcol = (tid & 31) * 4;
    const bool bok = (bn + bcol) < N;

    float acc[8][8];
#pragma unroll
    for (int i = 0; i < 8; ++i)
#pragma unroll
        for (int j = 0; j < 8; ++j) acc[i][j] = 0.f;

    const int nchunk = K >> 3;
    const float4 z4 = make_float4(0.f, 0.f, 0.f, 0.f);

#define ST_TR(DST, V, ROW, KQ)                                                  \
    DST[(KQ) + 0][ROW] = (V).x;  DST[(KQ) + 1][ROW] = (V).y;                    \
    DST[(KQ) + 2][ROW] = (V).z;  DST[(KQ) + 3][ROW] = (V).w;

    {
        float4 av = *(const float4*)(A + (size_t)(bm + arow) * K + akq);
        float4 bv = bok ? *(const float4*)(B + (size_t)brow * N + bn + bcol) : z4;
        ST_TR(As[0], av, arow, akq);
        *(float4*)&Bs[0][brow][bcol] = bv;
    }
    __syncthreads();

    for (int t = 0; t < nchunk; ++t) {
        const int buf = t & 1;
        const bool more = (t + 1 < nchunk);
        float4 av, bv;
        if (more) {
            const int k0 = (t + 1) << 3;
            av = *(const float4*)(A + (size_t)(bm + arow) * K + k0 + akq);
            bv = bok ? *(const float4*)(B + (size_t)(k0 + brow) * N + bn + bcol) : z4;
        }
#pragma unroll
        for (int kk = 0; kk < 8; ++kk) {
            float a[8], bb[8];
            *(float4*)&a[0]  = *(const float4*)&As[buf][kk][ty * 8];
            *(float4*)&a[4]  = *(const float4*)&As[buf][kk][ty * 8 + 4];
            *(float4*)&bb[0] = *(const float4*)&Bs[buf][kk][tx * 8];
            *(float4*)&bb[4] = *(const float4*)&Bs[buf][kk][tx * 8 + 4];
#pragma unroll
            for (int i = 0; i < 8; ++i)
#pragma unroll
                for (int j = 0; j < 8; ++j) acc[i][j] += a[i] * bb[j];
        }
        if (more) {
            const int nb = buf ^ 1;
            ST_TR(As[nb], av, arow, akq);
            *(float4*)&Bs[nb][brow][bcol] = bv;
            __syncthreads();
        }
    }
#undef ST_TR

#pragma unroll
    for (int i = 0; i < 8; ++i) {
        const int row = bm + ty * 8 + i;
        const int col = bn + tx * 8;
#pragma unroll
        for (int h = 0; h < 2; ++h) {
            if (col + h * 4 < N) {
                float4 vv = *(float4*)&acc[i][h * 4];
                if (BIAS) {
                    const float4 bi = *(const float4*)(bias + col + h * 4);
                    vv.x += bi.x; vv.y += bi.y; vv.z += bi.z; vv.w += bi.w;
                }
                if (RELU) {
                    vv.x = fmaxf(vv.x, 0.f); vv.y = fmaxf(vv.y, 0.f);
                    vv.z = fmaxf(vv.z, 0.f); vv.w = fmaxf(vv.w, 0.f);
                }
                *(float4*)(C + (size_t)row * N + col + h * 4) = vv;
            }
        }
    }
}

// ---------------- row softmax: fp32 out + split bf16 out ----------------------
__global__ void __launch_bounds__(256)
softmax_kernel(const float* __restrict__ logits, float* __restrict__ dst,
               bf16* __restrict__ dh, bf16* __restrict__ dl)
{
    const size_t row = blockIdx.x;
    const float* rp = logits + row * Sn;
    const int tid = threadIdx.x;

    __shared__ float sd[8];

    float v[8];
    float mx = -CUDART_INF_F;
#pragma unroll
    for (int j = 0; j < 8; ++j) {
        v[j] = rp[tid + 256 * j];
        mx = fmaxf(mx, v[j]);
    }
#pragma unroll
    for (int o = 16; o; o >>= 1) mx = fmaxf(mx, __shfl_xor_sync(0xffffffffu, mx, o));
    if ((tid & 31) == 0) sd[tid >> 5] = mx;
    __syncthreads();
    if (tid < 32) {
        float x = (tid < 8) ? sd[tid] : -CUDART_INF_F;
#pragma unroll
        for (int o = 4; o; o >>= 1) x = fmaxf(x, __shfl_xor_sync(0xffffffffu, x, o));
        if (tid == 0) sd[0] = x;
    }
    __syncthreads();
    mx = sd[0];
    __syncthreads();

    float s = 0.f;
#pragma unroll
    for (int j = 0; j < 8; ++j) {
        v[j] = __expf(v[j] - mx);
        s += v[j];
    }
#pragma unroll
    for (int o = 16; o; o >>= 1) s += __shfl_xor_sync(0xffffffffu, s, o);
    if ((tid & 31) == 0) sd[tid >> 5] = s;
    __syncthreads();
    if (tid < 32) {
        float x = (tid < 8) ? sd[tid] : 0.f;
#pragma unroll
        for (int o = 4; o; o >>= 1) x += __shfl_xor_sync(0xffffffffu, x, o);
        if (tid == 0) sd[0] = x;
    }
    __syncthreads();
    const float inv = 1.f / sd[0];

#pragma unroll
    for (int j = 0; j < 8; ++j) {
        const float a = v[j] * inv;
        const size_t o = row * Sn + tid + 256 * j;
        dst[o] = a;
        bf16 hi, lo;
        split_bf16(a, hi, lo);
        dh[o] = hi;
        dl[o] = lo;
    }
}

// ---------------- launch --------------------------------------------------------
extern "C" void kernel_launch(void* const* d_in, const int* in_sizes, int n_in,
                              void* d_out_v, int out_size)
{
    (void)in_sizes; (void)n_in;
    const float* query = (const float*)d_in[0];
    const float* key   = (const float*)d_in[1];
    const float* value = (const float*)d_in[2];
    const float* w1    = (const float*)d_in[3];
    const float* b1    = (const float*)d_in[4];
    const float* w2    = (const float*)d_in[5];
    const float* b2    = (const float*)d_in[6];
    const float* wq    = (const float*)d_in[7];
    const float* bq    = (const float*)d_in[8];
    const float* wk    = (const float*)d_in[9];
    const float* bk    = (const float*)d_in[10];
    float* d_out = (float*)d_out_v;

#define SYM(var, sym) cudaGetSymbolAddress((void**)&var, sym)
    bf16 *queryh, *queryl, *keyh, *keyl, *qh, *ql, *kh, *kl;
    bf16 *wqth, *wqtl, *wkth, *wktl, *w2th, *w2tl, *hh, *hl;
    bf16 *attnh, *attnl, *vth, *vtl;
    float *hf, *logits;
    SYM(queryh, g_queryh); SYM(queryl, g_queryl);
    SYM(keyh, g_keyh);     SYM(keyl, g_keyl);
    SYM(qh, g_qh); SYM(ql, g_ql); SYM(kh, g_kh); SYM(kl, g_kl);
    SYM(wqth, g_wqth); SYM(wqtl, g_wqtl);
    SYM(wkth, g_wkth); SYM(wktl, g_wktl);
    SYM(w2th, g_w2th); SYM(w2tl, g_w2tl);
    SYM(hh, g_hh); SYM(hl, g_hl);
    SYM(attnh, g_attnh); SYM(attnl, g_attnl);
    SYM(vth, g_vth); SYM(vtl, g_vtl);
    SYM(hf, g_hf); SYM(logits, g_logits);
#undef SYM

    const long long BSD = (long long)Bn * Sn * Dn;
    const long long BSS = (long long)Bn * Sn * Sn;

    float* out_ptr  = nullptr;
    float* attn_ptr = nullptr;
    if ((long long)out_size == BSD + BSS) { out_ptr = d_out; attn_ptr = d_out + BSD; }
    else if ((long long)out_size == BSS)  { attn_ptr = d_out; }
    else                                  { out_ptr = d_out; }

    // -- pre-transposes + splits --
    transpose_split<<<dim3(Dn / 32, Dn / 32, 1), dim3(32, 8)>>>(wq, wqth, wqtl, Dn, Dn, 0, 0);
    transpose_split<<<dim3(Dn / 32, Dn / 32, 1), dim3(32, 8)>>>(wk, wkth, wktl, Dn, Dn, 0, 0);
    transpose_split<<<dim3(Sn / 32, 2, 1), dim3(32, 8)>>>(w2, w2th, w2tl, Hn, Sn, 0, 0);
    transpose_split<<<dim3(Dn / 32, Sn / 32, Bn), dim3(32, 8)>>>(
        value, vth, vtl, Sn, Dn, (long long)Sn * Dn, (long long)Sn * Dn);

    convert_split<<<(Mn * (Dn / 4) + 255) / 256, 256>>>(query, queryh, queryl, Mn * (Dn / 4));
    convert_split<<<(Mn * (Dn / 4) + 255) / 256, 256>>>(key, keyh, keyl, Mn * (Dn / 4));

    // -- h = relu(query @ w1 + b1)  [M,64] fp32, then split --
    sgemm_nn<true, true><<<dim3(1, Mn / 128, 1), 256>>>(query, w1, b1, hf, Mn, Hn, Dn);
    convert_split<<<(Mn * (Hn / 4) + 255) / 256, 256>>>(hf, hh, hl, Mn * (Hn / 4));

    // -- q = query @ wqt^T + bq  -> split bf16 --
    bf16_nt<false, true, true><<<dim3(Dn / 128, Mn / 128, 1), 256>>>(
        queryh, queryl, wqth, wqtl, nullptr, nullptr, nullptr, nullptr,
        bq, nullptr, qh, ql,
        Dn, Dn, Dn, Dn, 0, 0, 0, 0, 0, 0, 0);

    // -- k = key @ wkt^T + bk  -> split bf16 --
    bf16_nt<false, true, true><<<dim3(Dn / 128, Mn / 128, 1), 256>>>(
        keyh, keyl, wkth, wktl, nullptr, nullptr, nullptr, nullptr,
        bk, nullptr, kh, kl,
        Dn, Dn, Dn, Dn, 0, 0, 0, 0, 0, 0, 0);

    // -- logits = q@k^T + h@w2t^T + b2  [B,S,S] fp32 --
    bf16_nt<true, true, false><<<dim3(Sn / 128, Sn / 128, Bn), 256>>>(
        qh, ql, kh, kl, hh, hl, w2th, w2tl,
        b2, logits, nullptr, nullptr,
        Sn, Dn, Dn, Dn, Hn, Hn, Hn,
        (long long)Sn * Dn, (long long)Sn * Dn, (long long)Sn * Sn, (long long)Sn * Hn);

    // -- attention = softmax(logits): fp32 (+ split bf16) --
    float* attn_final = attn_ptr ? attn_ptr : logits;
    softmax_kernel<<<Bn * Sn, 256>>>(logits, attn_final, attnh, attnl);

    // -- out = attention @ vt^T  [B,S,D] fp32 --
    if (out_ptr) {
        bf16_nt<false, false, false><<<dim3(Dn / 128, Sn / 128, Bn), 256>>>(
            attnh, attnl, vth, vtl, nullptr, nullptr, nullptr, nullptr,
            nullptr, out_ptr, nullptr, nullptr,
            Dn, Sn, Sn, Sn, 0, 0, 0,
            (long long)Sn * Sn, (long long)Dn * Sn, (long long)Sn * Dn, 0);
    }
}

// round 7
// speedup vs baseline: 3.5601x; 1.1382x over previous
#include <cuda_runtime.h>
#include <cuda_bf16.h>
#include <math_constants.h>
#include <cstdint>

#define Bn 16
#define Sn 2048
#define Dn 1024
#define Hn 64
#define Mn (Bn * Sn)   // 32768

typedef __nv_bfloat16 bf16;

// ---------------- scratch (device globals; no allocations allowed) ----------
__device__ __align__(16) bf16  g_queryh[(size_t)Mn * Dn], g_queryl[(size_t)Mn * Dn];
__device__ __align__(16) bf16  g_keyh[(size_t)Mn * Dn],   g_keyl[(size_t)Mn * Dn];
__device__ __align__(16) bf16  g_Rh[(size_t)Mn * Dn],     g_Rl[(size_t)Mn * Dn];
__device__ __align__(16) bf16  g_wqh[Dn * Dn], g_wql[Dn * Dn];
__device__ __align__(16) bf16  g_wkh[Dn * Dn], g_wkl[Dn * Dn];
__device__ __align__(16) bf16  g_Ph[Dn * Dn],  g_Pl[Dn * Dn];
__device__ __align__(16) bf16  g_w2th[Sn * Hn], g_w2tl[Sn * Hn];
__device__ __align__(16) bf16  g_hh[(size_t)Mn * Hn], g_hl[(size_t)Mn * Hn];
__device__ __align__(16) bf16  g_attnh[(size_t)Bn * Sn * Sn], g_attnl[(size_t)Bn * Sn * Sn];
__device__ __align__(16) bf16  g_vth[(size_t)Bn * Dn * Sn],   g_vtl[(size_t)Bn * Dn * Sn];
__device__ __align__(16) float g_hf[(size_t)Mn * Hn];
__device__ __align__(16) float g_logits[(size_t)Bn * Sn * Sn];
__device__ __align__(16) float g_u[Dn], g_v[Dn];        // wq*bk, wk*bq
__device__ __align__(16) float g_c[Mn], g_d[Mn];        // Q*u (+bb), K*v
__device__ __align__(16) float g_bb[4];                 // bq . bk

// ---------------- helpers -----------------------------------------------------
__device__ __forceinline__ void split_bf16(float x, bf16& hi, bf16& lo) {
    hi = __float2bfloat16_rn(x);
    lo = __float2bfloat16_rn(x - __bfloat162float(hi));
}

__device__ __forceinline__ void ldsm_x4(uint32_t& r0, uint32_t& r1, uint32_t& r2, uint32_t& r3,
                                        const void* p) {
    uint32_t addr = (uint32_t)__cvta_generic_to_shared(p);
    asm volatile("ldmatrix.sync.aligned.m8n8.x4.shared.b16 {%0,%1,%2,%3}, [%4];"
                 : "=r"(r0), "=r"(r1), "=r"(r2), "=r"(r3) : "r"(addr));
}

__device__ __forceinline__ void mma_bf16(float4& d, const uint32_t* a, const uint32_t* b) {
    asm volatile(
        "mma.sync.aligned.m16n8k16.row.col.f32.bf16.bf16.f32 "
        "{%0,%1,%2,%3}, {%4,%5,%6,%7}, {%8,%9}, {%0,%1,%2,%3};"
        : "+f"(d.x), "+f"(d.y), "+f"(d.z), "+f"(d.w)
        : "r"(a[0]), "r"(a[1]), "r"(a[2]), "r"(a[3]), "r"(b[0]), "r"(b[1]));
}

// =============================================================================
// bf16 3x-split NT GEMM: C[M,N] = (Ah+Al)[M,K] * ((Bh+Bl)[N,K])^T
// optional: fused phase2 += A2*B2^T ; col bias ; row/col correction vectors ;
// output fp32 or split bf16 hi/lo.
// CTA 128x128, warp 64x32, BK=32 bf16, double-buffered, ldmatrix + m16n8k16.
// =============================================================================
#define TSTR 40   // smem row stride in bf16 (80 B: 16B-aligned, conflict-free LDSM)

template <bool PHASE2, bool BIAS, bool SPLITOUT, bool ROWCOL>
__global__ void __launch_bounds__(256)
bf16_nt(const bf16* __restrict__ Ah_g, const bf16* __restrict__ Al_g,
        const bf16* __restrict__ Bh_g, const bf16* __restrict__ Bl_g,
        const bf16* __restrict__ A2h,  const bf16* __restrict__ A2l,
        const bf16* __restrict__ B2h,  const bf16* __restrict__ B2l,
        const float* __restrict__ bias,
        const float* __restrict__ rowv, const float* __restrict__ colv,
        float* __restrict__ C, bf16* __restrict__ Ch, bf16* __restrict__ Cl,
        int ldc, int K1, int lda, int ldb, int K2, int lda2, int ldb2,
        long long sA, long long sB, long long sC, long long sA2)
{
    Ah_g += (size_t)blockIdx.z * sA;  Al_g += (size_t)blockIdx.z * sA;
    Bh_g += (size_t)blockIdx.z * sB;  Bl_g += (size_t)blockIdx.z * sB;
    if (PHASE2) { A2h += (size_t)blockIdx.z * sA2; A2l += (size_t)blockIdx.z * sA2; }
    if (ROWCOL) { rowv += (size_t)blockIdx.z * Sn; colv += (size_t)blockIdx.z * Sn; }
    const size_t cof = (size_t)blockIdx.z * sC;

    // [buf][mat: 0=Ah 1=Al 2=Bh 3=Bl][row][k]
    __shared__ bf16 sm[2][4][128][TSTR];

    const int tid  = threadIdx.x;
    const int lane = tid & 31;
    const int wid  = tid >> 5;
    const int wm   = (wid & 1) * 64;
    const int wn   = (wid >> 1) * 32;
    const int bm   = blockIdx.y * 128;
    const int bn   = blockIdx.x * 128;

    const int l_row  = tid >> 1;
    const int l_half = (tid & 1) * 16;

    const int a_r = lane & 15;
    const int a_c = (lane >> 4) * 8;
    const int b_r = ((lane >> 4) & 1) * 8 + (lane & 7);
    const int b_c = ((lane >> 3) & 1) * 8;

    float4 acc[4][4];
#pragma unroll
    for (int i = 0; i < 4; ++i)
#pragma unroll
        for (int j = 0; j < 4; ++j) acc[i][j] = make_float4(0.f, 0.f, 0.f, 0.f);

    const int nch1 = K1 >> 5;
    const int nch  = nch1 + (PHASE2 ? (K2 >> 5) : 0);

    uint4 v[4][2];

#define G_LOAD(T)                                                                   \
    {                                                                               \
        const int _t = (T);                                                         \
        const bf16 *pa_h, *pa_l, *pb_h, *pb_l;                                      \
        if (!PHASE2 || _t < nch1) {                                                 \
            const int k0 = _t * 32 + l_half;                                        \
            pa_h = Ah_g + (size_t)(bm + l_row) * lda + k0;                          \
            pa_l = Al_g + (size_t)(bm + l_row) * lda + k0;                          \
            pb_h = Bh_g + (size_t)(bn + l_row) * ldb + k0;                          \
            pb_l = Bl_g + (size_t)(bn + l_row) * ldb + k0;                          \
        } else {                                                                    \
            const int k0 = (_t - nch1) * 32 + l_half;                               \
            pa_h = A2h + (size_t)(bm + l_row) * lda2 + k0;                          \
            pa_l = A2l + (size_t)(bm + l_row) * lda2 + k0;                          \
            pb_h = B2h + (size_t)(bn + l_row) * ldb2 + k0;                          \
            pb_l = B2l + (size_t)(bn + l_row) * ldb2 + k0;                          \
        }                                                                           \
        v[0][0] = *(const uint4*)pa_h;  v[0][1] = *(const uint4*)(pa_h + 8);        \
        v[1][0] = *(const uint4*)pa_l;  v[1][1] = *(const uint4*)(pa_l + 8);        \
        v[2][0] = *(const uint4*)pb_h;  v[2][1] = *(const uint4*)(pb_h + 8);        \
        v[3][0] = *(const uint4*)pb_l;  v[3][1] = *(const uint4*)(pb_l + 8);        \
    }

#define S_STORE(BUF)                                                                \
    _Pragma("unroll")                                                               \
    for (int m = 0; m < 4; ++m) {                                                   \
        *(uint4*)&sm[BUF][m][l_row][l_half]     = v[m][0];                          \
        *(uint4*)&sm[BUF][m][l_row][l_half + 8] = v[m][1];                          \
    }

    G_LOAD(0);
    S_STORE(0);
    __syncthreads();

    for (int t = 0; t < nch; ++t) {
        const int buf = t & 1;
        const bool more = (t + 1 < nch);
        if (more) G_LOAD(t + 1);

#pragma unroll
        for (int kk = 0; kk < 2; ++kk) {
            const int kb = kk * 16;

            uint32_t ah[4][4], al[4][4], bh[4][2], bl[4][2];
#pragma unroll
            for (int mi = 0; mi < 4; ++mi) {
                ldsm_x4(ah[mi][0], ah[mi][1], ah[mi][2], ah[mi][3],
                        &sm[buf][0][wm + mi * 16 + a_r][kb + a_c]);
                ldsm_x4(al[mi][0], al[mi][1], al[mi][2], al[mi][3],
                        &sm[buf][1][wm + mi * 16 + a_r][kb + a_c]);
            }
#pragma unroll
            for (int p = 0; p < 2; ++p) {
                ldsm_x4(bh[2 * p][0], bh[2 * p][1], bh[2 * p + 1][0], bh[2 * p + 1][1],
                        &sm[buf][2][wn + p * 16 + b_r][kb + b_c]);
                ldsm_x4(bl[2 * p][0], bl[2 * p][1], bl[2 * p + 1][0], bl[2 * p + 1][1],
                        &sm[buf][3][wn + p * 16 + b_r][kb + b_c]);
            }

#pragma unroll
            for (int mi = 0; mi < 4; ++mi)
#pragma unroll
                for (int ni = 0; ni < 4; ++ni) {
                    mma_bf16(acc[mi][ni], ah[mi], bl[ni]);
                    mma_bf16(acc[mi][ni], al[mi], bh[ni]);
                    mma_bf16(acc[mi][ni], ah[mi], bh[ni]);
                }
        }

        if (more) {
            S_STORE(buf ^ 1);
            __syncthreads();
        }
    }
#undef G_LOAD
#undef S_STORE

    const int er = lane >> 2;
    const int ec = (lane & 3) * 2;
#pragma unroll
    for (int mi = 0; mi < 4; ++mi) {
        const int row = bm + wm + mi * 16 + er;
        float r0 = 0.f, r1 = 0.f;
        if (ROWCOL) { r0 = rowv[row]; r1 = rowv[row + 8]; }
#pragma unroll
        for (int ni = 0; ni < 4; ++ni) {
            const int col = bn + wn + ni * 8 + ec;
            float2 v0 = make_float2(acc[mi][ni].x, acc[mi][ni].y);
            float2 v1 = make_float2(acc[mi][ni].z, acc[mi][ni].w);
            if (BIAS) {
                const float2 bi = *(const float2*)(bias + col);
                v0.x += bi.x; v0.y += bi.y;
                v1.x += bi.x; v1.y += bi.y;
            }
            if (ROWCOL) {
                const float2 cv = *(const float2*)(colv + col);
                v0.x += cv.x + r0; v0.y += cv.y + r0;
                v1.x += cv.x + r1; v1.y += cv.y + r1;
            }
            if (SPLITOUT) {
                __nv_bfloat162 h2, l2;
                split_bf16(v0.x, h2.x, l2.x);  split_bf16(v0.y, h2.y, l2.y);
                *(__nv_bfloat162*)(Ch + cof + (size_t)row * ldc + col) = h2;
                *(__nv_bfloat162*)(Cl + cof + (size_t)row * ldc + col) = l2;
                split_bf16(v1.x, h2.x, l2.x);  split_bf16(v1.y, h2.y, l2.y);
                *(__nv_bfloat162*)(Ch + cof + (size_t)(row + 8) * ldc + col) = h2;
                *(__nv_bfloat162*)(Cl + cof + (size_t)(row + 8) * ldc + col) = l2;
            } else {
                *(float2*)(C + cof + (size_t)row * ldc + col)       = v0;
                *(float2*)(C + cof + (size_t)(row + 8) * ldc + col) = v1;
            }
        }
    }
}

// ---------------- transpose fp32 -> split bf16 hi/lo -------------------------
__global__ void transpose_split(const float* __restrict__ in,
                                bf16* __restrict__ oh, bf16* __restrict__ ol,
                                int R, int C, long long sIn, long long sOut)
{
    __shared__ float t[32][33];
    in += (size_t)blockIdx.z * sIn;
    oh += (size_t)blockIdx.z * sOut;
    ol += (size_t)blockIdx.z * sOut;
    const int r0 = blockIdx.y * 32, c0 = blockIdx.x * 32;
    const int x = threadIdx.x, y = threadIdx.y;
#pragma unroll
    for (int i = y; i < 32; i += 8)
        if (r0 + i < R && c0 + x < C) t[i][x] = in[(size_t)(r0 + i) * C + c0 + x];
    __syncthreads();
#pragma unroll
    for (int i = y; i < 32; i += 8)
        if (c0 + i < C && r0 + x < R) {
            bf16 hi, lo;
            split_bf16(t[x][i], hi, lo);
            oh[(size_t)(c0 + i) * R + r0 + x] = hi;
            ol[(size_t)(c0 + i) * R + r0 + x] = lo;
        }
}

// ---------------- flat fp32 -> split bf16 hi/lo -------------------------------
__global__ void convert_split(const float* __restrict__ in,
                              bf16* __restrict__ oh, bf16* __restrict__ ol, int n4)
{
    const int i = blockIdx.x * 256 + threadIdx.x;
    if (i < n4) {
        const float4 f = ((const float4*)in)[i];
        __nv_bfloat162 h0, l0, h1, l1;
        split_bf16(f.x, h0.x, l0.x);  split_bf16(f.y, h0.y, l0.y);
        split_bf16(f.z, h1.x, l1.x);  split_bf16(f.w, h1.y, l1.y);
        ((__nv_bfloat162*)oh)[2 * i]     = h0;
        ((__nv_bfloat162*)oh)[2 * i + 1] = h1;
        ((__nv_bfloat162*)ol)[2 * i]     = l0;
        ((__nv_bfloat162*)ol)[2 * i + 1] = l1;
    }
}

// ---------------- small fp32 vector kernels ----------------------------------
__global__ void dot_vec(const float* __restrict__ a, const float* __restrict__ b,
                        float* __restrict__ out, int n)
{
    __shared__ float sd[8];
    float s = 0.f;
    for (int i = threadIdx.x; i < (n >> 2); i += 256) {
        const float4 x = ((const float4*)a)[i], y = ((const float4*)b)[i];
        s += x.x * y.x + x.y * y.y + x.z * y.z + x.w * y.w;
    }
#pragma unroll
    for (int o = 16; o; o >>= 1) s += __shfl_xor_sync(0xffffffffu, s, o);
    if ((threadIdx.x & 31) == 0) sd[threadIdx.x >> 5] = s;
    __syncthreads();
    if (threadIdx.x < 32) {
        float x = (threadIdx.x < 8) ? sd[threadIdx.x] : 0.f;
#pragma unroll
        for (int o = 4; o; o >>= 1) x += __shfl_xor_sync(0xffffffffu, x, o);
        if (threadIdx.x == 0) out[0] = x;
    }
}

// y[row] = dot(Mt[row,:], x) (+ addc[0] if given); blockDim (32,8)
__global__ void gemv_rows(const float* __restrict__ Mt, const float* __restrict__ x,
                          float* __restrict__ y, int C, const float* __restrict__ addc)
{
    const int row = blockIdx.x * 8 + threadIdx.y;
    const float* rp = Mt + (size_t)row * C;
    float s = 0.f;
    for (int j = threadIdx.x; j < (C >> 2); j += 32) {
        const float4 a = ((const float4*)rp)[j];
        const float4 b = ((const float4*)x)[j];
        s += a.x * b.x + a.y * b.y + a.z * b.z + a.w * b.w;
    }
#pragma unroll
    for (int o = 16; o; o >>= 1) s += __shfl_xor_sync(0xffffffffu, s, o);
    if (threadIdx.x == 0) y[row] = s + (addc ? addc[0] : 0.f);
}

// ---------------- FFMA SGEMM for h = relu(query@w1+b1) ------------------------
#define APAD 132
template <bool RELU, bool BIAS>
__global__ void __launch_bounds__(256, 2)
sgemm_nn(const float* __restrict__ A, const float* __restrict__ B,
         const float* __restrict__ bias, float* __restrict__ C,
         int M, int N, int K)
{
    __shared__ float As[2][8][APAD];
    __shared__ float Bs[2][8][128];

    const int tid = threadIdx.x;
    const int bm = blockIdx.y * 128;
    const int bn = blockIdx.x * 128;
    const int tx = tid & 15;
    const int ty = tid >> 4;

    const int arow = tid >> 1;
    const int akq  = (tid & 1) * 4;
    const int brow = tid >> 5;
    const int bcol = (tid & 31) * 4;
    const bool bok = (bn + bcol) < N;

    float acc[8][8];
#pragma unroll
    for (int i = 0; i < 8; ++i)
#pragma unroll
        for (int j = 0; j < 8; ++j) acc[i][j] = 0.f;

    const int nchunk = K >> 3;
    const float4 z4 = make_float4(0.f, 0.f, 0.f, 0.f);

#define ST_TR(DST, V, ROW, KQ)                                                  \
    DST[(KQ) + 0][ROW] = (V).x;  DST[(KQ) + 1][ROW] = (V).y;                    \
    DST[(KQ) + 2][ROW] = (V).z;  DST[(KQ) + 3][ROW] = (V).w;

    {
        float4 av = *(const float4*)(A + (size_t)(bm + arow) * K + akq);
        float4 bv = bok ? *(const float4*)(B + (size_t)brow * N + bn + bcol) : z4;
        ST_TR(As[0], av, arow, akq);
        *(float4*)&Bs[0][brow][bcol] = bv;
    }
    __syncthreads();

    for (int t = 0; t < nchunk; ++t) {
        const int buf = t & 1;
        const bool more = (t + 1 < nchunk);
        float4 av, bv;
        if (more) {
            const int k0 = (t + 1) << 3;
            av = *(const float4*)(A + (size_t)(bm + arow) * K + k0 + akq);
            bv = bok ? *(const float4*)(B + (size_t)(k0 + brow) * N + bn + bcol) : z4;
        }
#pragma unroll
        for (int kk = 0; kk < 8; ++kk) {
            float a[8], bb[8];
            *(float4*)&a[0]  = *(const float4*)&As[buf][kk][ty * 8];
            *(float4*)&a[4]  = *(const float4*)&As[buf][kk][ty * 8 + 4];
            *(float4*)&bb[0] = *(const float4*)&Bs[buf][kk][tx * 8];
            *(float4*)&bb[4] = *(const float4*)&Bs[buf][kk][tx * 8 + 4];
#pragma unroll
            for (int i = 0; i < 8; ++i)
#pragma unroll
                for (int j = 0; j < 8; ++j) acc[i][j] += a[i] * bb[j];
        }
        if (more) {
            const int nb = buf ^ 1;
            ST_TR(As[nb], av, arow, akq);
            *(float4*)&Bs[nb][brow][bcol] = bv;
            __syncthreads();
        }
    }
#undef ST_TR

#pragma unroll
    for (int i = 0; i < 8; ++i) {
        const int row = bm + ty * 8 + i;
        const int col = bn + tx * 8;
#pragma unroll
        for (int h = 0; h < 2; ++h) {
            if (col + h * 4 < N) {
                float4 vv = *(float4*)&acc[i][h * 4];
                if (BIAS) {
                    const float4 bi = *(const float4*)(bias + col + h * 4);
                    vv.x += bi.x; vv.y += bi.y; vv.z += bi.z; vv.w += bi.w;
                }
                if (RELU) {
                    vv.x = fmaxf(vv.x, 0.f); vv.y = fmaxf(vv.y, 0.f);
                    vv.z = fmaxf(vv.z, 0.f); vv.w = fmaxf(vv.w, 0.f);
                }
                *(float4*)(C + (size_t)row * N + col + h * 4) = vv;
            }
        }
    }
}

// ---------------- row softmax: fp32 out + split bf16 out ----------------------
__global__ void __launch_bounds__(256)
softmax_kernel(const float* __restrict__ logits, float* __restrict__ dst,
               bf16* __restrict__ dh, bf16* __restrict__ dl)
{
    const size_t row = blockIdx.x;
    const float* rp = logits + row * Sn;
    const int tid = threadIdx.x;

    __shared__ float sd[8];

    float v[8];
    float mx = -CUDART_INF_F;
#pragma unroll
    for (int j = 0; j < 8; ++j) {
        v[j] = rp[tid + 256 * j];
        mx = fmaxf(mx, v[j]);
    }
#pragma unroll
    for (int o = 16; o; o >>= 1) mx = fmaxf(mx, __shfl_xor_sync(0xffffffffu, mx, o));
    if ((tid & 31) == 0) sd[tid >> 5] = mx;
    __syncthreads();
    if (tid < 32) {
        float x = (tid < 8) ? sd[tid] : -CUDART_INF_F;
#pragma unroll
        for (int o = 4; o; o >>= 1) x = fmaxf(x, __shfl_xor_sync(0xffffffffu, x, o));
        if (tid == 0) sd[0] = x;
    }
    __syncthreads();
    mx = sd[0];
    __syncthreads();

    float s = 0.f;
#pragma unroll
    for (int j = 0; j < 8; ++j) {
        v[j] = __expf(v[j] - mx);
        s += v[j];
    }
#pragma unroll
    for (int o = 16; o; o >>= 1) s += __shfl_xor_sync(0xffffffffu, s, o);
    if ((tid & 31) == 0) sd[tid >> 5] = s;
    __syncthreads();
    if (tid < 32) {
        float x = (tid < 8) ? sd[tid] : 0.f;
#pragma unroll
        for (int o = 4; o; o >>= 1) x += __shfl_xor_sync(0xffffffffu, x, o);
        if (tid == 0) sd[0] = x;
    }
    __syncthreads();
    const float inv = 1.f / sd[0];

#pragma unroll
    for (int j = 0; j < 8; ++j) {
        const float a = v[j] * inv;
        const size_t o = row * Sn + tid + 256 * j;
        dst[o] = a;
        bf16 hi, lo;
        split_bf16(a, hi, lo);
        dh[o] = hi;
        dl[o] = lo;
    }
}

// ---------------- launch --------------------------------------------------------
extern "C" void kernel_launch(void* const* d_in, const int* in_sizes, int n_in,
                              void* d_out_v, int out_size)
{
    (void)in_sizes; (void)n_in;
    const float* query = (const float*)d_in[0];
    const float* key   = (const float*)d_in[1];
    const float* value = (const float*)d_in[2];
    const float* w1    = (const float*)d_in[3];
    const float* b1    = (const float*)d_in[4];
    const float* w2    = (const float*)d_in[5];
    const float* b2    = (const float*)d_in[6];
    const float* wq    = (const float*)d_in[7];
    const float* bq    = (const float*)d_in[8];
    const float* wk    = (const float*)d_in[9];
    const float* bk    = (const float*)d_in[10];
    float* d_out = (float*)d_out_v;

#define SYM(var, sym) cudaGetSymbolAddress((void**)&var, sym)
    bf16 *queryh, *queryl, *keyh, *keyl, *Rh, *Rl;
    bf16 *wqh, *wql, *wkh, *wkl, *Ph, *Pl, *w2th, *w2tl, *hh, *hl;
    bf16 *attnh, *attnl, *vth, *vtl;
    float *hf, *logits, *u, *v, *cvec, *dvec, *bb;
    SYM(queryh, g_queryh); SYM(queryl, g_queryl);
    SYM(keyh, g_keyh);     SYM(keyl, g_keyl);
    SYM(Rh, g_Rh); SYM(Rl, g_Rl);
    SYM(wqh, g_wqh); SYM(wql, g_wql);
    SYM(wkh, g_wkh); SYM(wkl, g_wkl);
    SYM(Ph, g_Ph); SYM(Pl, g_Pl);
    SYM(w2th, g_w2th); SYM(w2tl, g_w2tl);
    SYM(hh, g_hh); SYM(hl, g_hl);
    SYM(attnh, g_attnh); SYM(attnl, g_attnl);
    SYM(vth, g_vth); SYM(vtl, g_vtl);
    SYM(hf, g_hf); SYM(logits, g_logits);
    SYM(u, g_u); SYM(v, g_v); SYM(cvec, g_c); SYM(dvec, g_d); SYM(bb, g_bb);
#undef SYM

    const long long BSD = (long long)Bn * Sn * Dn;
    const long long BSS = (long long)Bn * Sn * Sn;

    float* out_ptr  = nullptr;
    float* attn_ptr = nullptr;
    if ((long long)out_size == BSD + BSS) { out_ptr = d_out; attn_ptr = d_out + BSD; }
    else if ((long long)out_size == BSS)  { attn_ptr = d_out; }
    else                                  { out_ptr = d_out; }

    // -- input converts / transposes --
    convert_split<<<(Mn * (Dn / 4) + 255) / 256, 256>>>(query, queryh, queryl, Mn * (Dn / 4));
    convert_split<<<(Mn * (Dn / 4) + 255) / 256, 256>>>(key, keyh, keyl, Mn * (Dn / 4));
    convert_split<<<(Dn * (Dn / 4) + 255) / 256, 256>>>(wq, wqh, wql, Dn * (Dn / 4));
    convert_split<<<(Dn * (Dn / 4) + 255) / 256, 256>>>(wk, wkh, wkl, Dn * (Dn / 4));
    transpose_split<<<dim3(Sn / 32, 2, 1), dim3(32, 8)>>>(w2, w2th, w2tl, Hn, Sn, 0, 0);
    transpose_split<<<dim3(Dn / 32, Sn / 32, Bn), dim3(32, 8)>>>(
        value, vth, vtl, Sn, Dn, (long long)Sn * Dn, (long long)Sn * Dn);

    // -- bias correction vectors: u = wq*bk, v = wk*bq, bb = bq.bk,
    //    c = Q*u + bb (row bias), d = K*v (col bias) --
    dot_vec<<<1, 256>>>(bq, bk, bb, Dn);
    gemv_rows<<<Dn / 8, dim3(32, 8)>>>(wq, bk, u, Dn, nullptr);
    gemv_rows<<<Dn / 8, dim3(32, 8)>>>(wk, bq, v, Dn, nullptr);
    gemv_rows<<<Mn / 8, dim3(32, 8)>>>(query, u, cvec, Dn, bb);
    gemv_rows<<<Mn / 8, dim3(32, 8)>>>(key, v, dvec, Dn, nullptr);

    // -- P = wq @ wk^T  [D,D] fp32 (temp in logits), then split --
    bf16_nt<false, false, false, false><<<dim3(Dn / 128, Dn / 128, 1), 256>>>(
        wqh, wql, wkh, wkl, nullptr, nullptr, nullptr, nullptr,
        nullptr, nullptr, nullptr, logits, nullptr, nullptr,
        Dn, Dn, Dn, Dn, 0, 0, 0, 0, 0, 0, 0);
    convert_split<<<(Dn * (Dn / 4) + 255) / 256, 256>>>(logits, Ph, Pl, Dn * (Dn / 4));

    // -- h = relu(query @ w1 + b1)  [M,64] fp32, then split --
    sgemm_nn<true, true><<<dim3(1, Mn / 128, 1), 256>>>(query, w1, b1, hf, Mn, Hn, Dn);
    convert_split<<<(Mn * (Hn / 4) + 255) / 256, 256>>>(hf, hh, hl, Mn * (Hn / 4));

    // -- R = key @ P^T  [M,D] -> split bf16 --
    bf16_nt<false, false, true, false><<<dim3(Dn / 128, Mn / 128, 1), 256>>>(
        keyh, keyl, Ph, Pl, nullptr, nullptr, nullptr, nullptr,
        nullptr, nullptr, nullptr, nullptr, Rh, Rl,
        Dn, Dn, Dn, Dn, 0, 0, 0, 0, 0, 0, 0);

    // -- logits = Q@R^T + h@w2t^T + b2 + c_row + d_col  [B,S,S] fp32 --
    bf16_nt<true, true, false, true><<<dim3(Sn / 128, Sn / 128, Bn), 256>>>(
        queryh, queryl, Rh, Rl, hh, hl, w2th, w2tl,
        b2, cvec, dvec, logits, nullptr, nullptr,
        Sn, Dn, Dn, Dn, Hn, Hn, Hn,
        (long long)Sn * Dn, (long long)Sn * Dn, (long long)Sn * Sn, (long long)Sn * Hn);

    // -- attention = softmax(logits): fp32 (+ split bf16) --
    float* attn_final = attn_ptr ? attn_ptr : logits;
    softmax_kernel<<<Bn * Sn, 256>>>(logits, attn_final, attnh, attnl);

    // -- out = attention @ vt^T  [B,S,D] fp32 --
    if (out_ptr) {
        bf16_nt<false, false, false, false><<<dim3(Dn / 128, Sn / 128, Bn), 256>>>(
            attnh, attnl, vth, vtl, nullptr, nullptr, nullptr, nullptr,
            nullptr, nullptr, nullptr, out_ptr, nullptr, nullptr,
            Dn, Sn, Sn, Sn, 0, 0, 0,
            (long long)Sn * Sn, (long long)Dn * Sn, (long long)Sn * Dn, 0);
    }
}